// round 1
// baseline (speedup 1.0000x reference)
#include <cuda_runtime.h>
#include <math.h>

#define Bb 2
#define Tt 4096
#define Cc 768
#define NHh 12
#define HSs 64
#define BT (Bb*Tt)
#define C3 (3*Cc)
#define LD 65   // padded smem row stride for 64-wide tiles (conflict-free)

// Scratch (device globals: no cudaMalloc allowed anywhere)
__device__ float g_qkv[(size_t)BT * C3];   // [B*T, 3C]
__device__ float g_att[(size_t)BT * Cc];   // [B*T, C] attention output (pre-proj)

// ---------------------------------------------------------------------------
// SGEMM: Cm[M,N] = A[M,K] * Bm[K,N], all row-major.
// Requires M%128==0, N%128==0, K%8==0. 256 threads, 128x128 tile, 8x8/thread.
// ---------------------------------------------------------------------------
__global__ __launch_bounds__(256, 2)
void sgemm128(const float* __restrict__ A, const float* __restrict__ Bm,
              float* __restrict__ Cm, int M, int N, int K)
{
    __shared__ float As[8][128];
    __shared__ float Bs[8][128];
    const int tid = threadIdx.x;
    const int tx = tid & 15, ty = tid >> 4;
    const int brow = blockIdx.y << 7;
    const int bcol = blockIdx.x << 7;

    const int arow = tid >> 1;          // 0..127
    const int acol = (tid & 1) << 2;    // 0 or 4
    const int bro  = tid >> 5;          // 0..7
    const int bco  = (tid & 31) << 2;   // 0..124 step 4

    const float* Ap = A + (size_t)(brow + arow) * K + acol;
    const float* Bp = Bm + (size_t)bro * N + (bcol + bco);

    float acc[8][8];
    #pragma unroll
    for (int i = 0; i < 8; i++)
        #pragma unroll
        for (int j = 0; j < 8; j++) acc[i][j] = 0.f;

    for (int k0 = 0; k0 < K; k0 += 8) {
        float4 av = *(const float4*)(Ap + k0);
        As[acol + 0][arow] = av.x;
        As[acol + 1][arow] = av.y;
        As[acol + 2][arow] = av.z;
        As[acol + 3][arow] = av.w;
        *(float4*)&Bs[bro][bco] = *(const float4*)(Bp + (size_t)k0 * N);
        __syncthreads();
        #pragma unroll
        for (int k = 0; k < 8; k++) {
            float4 a0 = *(const float4*)&As[k][ty << 3];
            float4 a1 = *(const float4*)&As[k][(ty << 3) + 4];
            float4 b0 = *(const float4*)&Bs[k][tx << 3];
            float4 b1 = *(const float4*)&Bs[k][(tx << 3) + 4];
            float a[8] = {a0.x, a0.y, a0.z, a0.w, a1.x, a1.y, a1.z, a1.w};
            float b[8] = {b0.x, b0.y, b0.z, b0.w, b1.x, b1.y, b1.z, b1.w};
            #pragma unroll
            for (int i = 0; i < 8; i++)
                #pragma unroll
                for (int j = 0; j < 8; j++)
                    acc[i][j] = fmaf(a[i], b[j], acc[i][j]);
        }
        __syncthreads();
    }
    #pragma unroll
    for (int i = 0; i < 8; i++) {
        float* Cp = Cm + (size_t)(brow + (ty << 3) + i) * N + bcol + (tx << 3);
        *(float4*)(Cp)     = make_float4(acc[i][0], acc[i][1], acc[i][2], acc[i][3]);
        *(float4*)(Cp + 4) = make_float4(acc[i][4], acc[i][5], acc[i][6], acc[i][7]);
    }
}

// ---------------------------------------------------------------------------
// Causal flash attention, fp32. One block per (q-tile of 64, head, batch).
// qkv layout: [B*T, 3C]; q cols [h*64, +64), k cols [C + h*64), v cols [2C + h*64).
// 256 threads: 16x16 grid, each thread 4x4 of the 64x64 tile.
// ---------------------------------------------------------------------------
__global__ __launch_bounds__(256, 2)
void flash_attn(const float* __restrict__ qkv, float* __restrict__ out)
{
    extern __shared__ float sm[];
    float* Qs  = sm;              // 64*LD
    float* Ks  = Qs + 64 * LD;
    float* Vs  = Ks + 64 * LD;
    float* Ss  = Vs + 64 * LD;
    float* m_s = Ss + 64 * LD;    // 64
    float* l_s = m_s + 64;        // 64
    float* a_s = l_s + 64;        // 64 (alpha per row)

    const int qblk = blockIdx.x;
    const int h    = blockIdx.y;
    const int b    = blockIdx.z;
    const int tid  = threadIdx.x;
    const int tx   = tid & 15, ty = tid >> 4;
    const float NEG = -1e30f;
    const float scale = 0.125f;   // 1/sqrt(64)

    const size_t qrow0 = (size_t)(b * Tt + qblk * 64);
    const float* qbase = qkv + qrow0 * C3 + h * HSs;

    // Load Q tile (stays resident) + init running stats
    #pragma unroll
    for (int it = 0; it < 4; it++) {
        int idx = tid + it * 256;           // 0..1023
        int r = idx >> 4, c4 = (idx & 15) << 2;
        float4 v = *(const float4*)(qbase + (size_t)r * C3 + c4);
        float* q = Qs + r * LD + c4;
        q[0] = v.x; q[1] = v.y; q[2] = v.z; q[3] = v.w;
    }
    if (tid < 64) { m_s[tid] = NEG; l_s[tid] = 0.f; }

    float acc[4][4];
    #pragma unroll
    for (int i = 0; i < 4; i++)
        #pragma unroll
        for (int j = 0; j < 4; j++) acc[i][j] = 0.f;

    for (int jb = 0; jb <= qblk; jb++) {
        __syncthreads();   // prior iter's reads of Ks/Vs/Ss done
        const float* kbase = qkv + (size_t)(b * Tt + jb * 64) * C3 + Cc + h * HSs;
        const float* vbase = kbase + Cc;
        #pragma unroll
        for (int it = 0; it < 4; it++) {
            int idx = tid + it * 256;
            int r = idx >> 4, c4 = (idx & 15) << 2;
            float4 kv = *(const float4*)(kbase + (size_t)r * C3 + c4);
            float* kd = Ks + r * LD + c4;
            kd[0] = kv.x; kd[1] = kv.y; kd[2] = kv.z; kd[3] = kv.w;
            float4 vv = *(const float4*)(vbase + (size_t)r * C3 + c4);
            float* vd = Vs + r * LD + c4;
            vd[0] = vv.x; vd[1] = vv.y; vd[2] = vv.z; vd[3] = vv.w;
        }
        __syncthreads();

        // S = Q * K^T  (4x4 per thread)
        float s4[4][4];
        #pragma unroll
        for (int i = 0; i < 4; i++)
            #pragma unroll
            for (int j = 0; j < 4; j++) s4[i][j] = 0.f;
        #pragma unroll 4
        for (int k = 0; k < 64; k++) {
            float a[4], bb[4];
            #pragma unroll
            for (int i = 0; i < 4; i++) a[i] = Qs[(ty * 4 + i) * LD + k];
            #pragma unroll
            for (int j = 0; j < 4; j++) bb[j] = Ks[(tx * 4 + j) * LD + k];
            #pragma unroll
            for (int i = 0; i < 4; i++)
                #pragma unroll
                for (int j = 0; j < 4; j++)
                    s4[i][j] = fmaf(a[i], bb[j], s4[i][j]);
        }
        const bool diag = (jb == qblk);
        #pragma unroll
        for (int i = 0; i < 4; i++)
            #pragma unroll
            for (int j = 0; j < 4; j++) {
                float s = s4[i][j] * scale;
                if (diag && (tx * 4 + j) > (ty * 4 + i)) s = NEG;
                Ss[(ty * 4 + i) * LD + tx * 4 + j] = s;
            }
        __syncthreads();

        // Online softmax: 4 threads per row, 16 cols each
        {
            int r = tid >> 2, p = tid & 3;
            float* row = Ss + r * LD + p * 16;
            float mx = NEG;
            #pragma unroll
            for (int c = 0; c < 16; c++) mx = fmaxf(mx, row[c]);
            mx = fmaxf(mx, __shfl_xor_sync(0xffffffffu, mx, 1));
            mx = fmaxf(mx, __shfl_xor_sync(0xffffffffu, mx, 2));
            float m_old = m_s[r];
            float m_new = fmaxf(m_old, mx);
            float sum = 0.f;
            #pragma unroll
            for (int c = 0; c < 16; c++) {
                float e = __expf(row[c] - m_new);
                row[c] = e;
                sum += e;
            }
            sum += __shfl_xor_sync(0xffffffffu, sum, 1);
            sum += __shfl_xor_sync(0xffffffffu, sum, 2);
            if (p == 0) {
                float alpha = __expf(m_old - m_new);
                m_s[r] = m_new;
                l_s[r] = l_s[r] * alpha + sum;
                a_s[r] = alpha;
            }
        }
        __syncthreads();

        // Rescale O accumulators, then O += P * V
        #pragma unroll
        for (int i = 0; i < 4; i++) {
            float alpha = a_s[ty * 4 + i];
            #pragma unroll
            for (int j = 0; j < 4; j++) acc[i][j] *= alpha;
        }
        #pragma unroll 4
        for (int k = 0; k < 64; k++) {
            float a[4], bb[4];
            #pragma unroll
            for (int i = 0; i < 4; i++) a[i] = Ss[(ty * 4 + i) * LD + k];
            #pragma unroll
            for (int j = 0; j < 4; j++) bb[j] = Vs[k * LD + tx * 4 + j];
            #pragma unroll
            for (int i = 0; i < 4; i++)
                #pragma unroll
                for (int j = 0; j < 4; j++)
                    acc[i][j] = fmaf(a[i], bb[j], acc[i][j]);
        }
    }

    // Write O / l to g_att in [B*T, C] layout (undoes the head transpose)
    float* obase = out + qrow0 * Cc + h * HSs;
    #pragma unroll
    for (int i = 0; i < 4; i++) {
        int r = ty * 4 + i;
        float rl = 1.f / l_s[r];
        *(float4*)(obase + (size_t)r * Cc + tx * 4) =
            make_float4(acc[i][0] * rl, acc[i][1] * rl, acc[i][2] * rl, acc[i][3] * rl);
    }
}

// ---------------------------------------------------------------------------
extern "C" void kernel_launch(void* const* d_in, const int* in_sizes, int n_in,
                              void* d_out, int out_size)
{
    const float* x      = (const float*)d_in[0];   // [B,T,C]
    const float* w_attn = (const float*)d_in[1];   // [C,3C]
    const float* w_proj = (const float*)d_in[2];   // [C,C]
    float* out = (float*)d_out;                    // [B,T,C]

    float *qkv, *att;
    cudaGetSymbolAddress((void**)&qkv, g_qkv);
    cudaGetSymbolAddress((void**)&att, g_att);

    const size_t FLASH_SMEM = (size_t)(4 * 64 * LD + 3 * 64) * sizeof(float); // ~67 KB
    cudaFuncSetAttribute(flash_attn, cudaFuncAttributeMaxDynamicSharedMemorySize,
                         (int)FLASH_SMEM);

    // 1) QKV projection: [8192,768] @ [768,2304]
    sgemm128<<<dim3(C3 / 128, BT / 128), 256>>>(x, w_attn, qkv, BT, C3, Cc);
    // 2) Causal flash attention
    flash_attn<<<dim3(Tt / 64, NHh, Bb), 256, FLASH_SMEM>>>(qkv, att);
    // 3) Output projection: [8192,768] @ [768,768]
    sgemm128<<<dim3(Cc / 128, BT / 128), 256>>>(att, w_proj, out, BT, Cc, Cc);
}

// round 2
// speedup vs baseline: 2.4217x; 2.4217x over previous
#include <cuda_runtime.h>
#include <math.h>
#include <stdint.h>

#define Bb 2
#define Tt 4096
#define Cc 768
#define NHh 12
#define HSs 64
#define BT (Bb*Tt)
#define C3 (3*Cc)

// Scratch (device globals: no cudaMalloc allowed anywhere)
__device__ float g_qkv[(size_t)BT * C3];   // [B*T, 3C]
__device__ float g_att[(size_t)BT * Cc];   // [B*T, C]

__device__ __forceinline__ float tf32r(float x) {
    uint32_t u;
    asm("cvt.rna.tf32.f32 %0, %1;" : "=r"(u) : "f"(x));
    return __uint_as_float(u);
}
__device__ __forceinline__ uint32_t fbits(float x) { return __float_as_uint(x); }

__device__ __forceinline__ void mma_tf32(float c[4], const uint32_t a[4], const uint32_t b[2]) {
    asm volatile(
        "mma.sync.aligned.m16n8k8.row.col.f32.tf32.tf32.f32 "
        "{%0,%1,%2,%3},{%4,%5,%6,%7},{%8,%9},{%0,%1,%2,%3};"
        : "+f"(c[0]), "+f"(c[1]), "+f"(c[2]), "+f"(c[3])
        : "r"(a[0]), "r"(a[1]), "r"(a[2]), "r"(a[3]), "r"(b[0]), "r"(b[1]));
}

// ---------------------------------------------------------------------------
// TF32 GEMM: C[M,N] = A[M,K] * B[K,N], row-major. M%128==0, N%128==0, K%16==0.
// 256 threads, 128x128 tile, warp grid 2x4 (warp tile 64x32).
// ---------------------------------------------------------------------------
#define LDA 20    // 16 + 4: A frag banks (4r+c)%32 unique
#define LDB 136   // 128 + 8: B frag banks (8k+n)%32 unique

__global__ __launch_bounds__(256, 2)
void gemm_tf32(const float* __restrict__ A, const float* __restrict__ B,
               float* __restrict__ C, int M, int N, int K)
{
    __shared__ float As[128 * LDA];   // [m][k], kc=16
    __shared__ float Bs[16 * LDB];    // [k][n]

    const int tid = threadIdx.x;
    const int lane = tid & 31, wid = tid >> 5;
    const int warpM = wid >> 2, warpN = wid & 3;
    const int lr = lane >> 2, lc = lane & 3;
    const int brow = blockIdx.y << 7, bcol = blockIdx.x << 7;

    const int ar = tid >> 2;          // 0..63 (+64 second pass)
    const int ac = (tid & 3) << 2;    // 0,4,8,12
    const int br = tid >> 5;          // 0..7 (+8 second pass)
    const int bc = lane << 2;         // 0..124

    const float* Ab = A + (size_t)brow * K;
    const float* Bbp = B + bcol;

    float acc[4][4][4];
    #pragma unroll
    for (int i = 0; i < 4; i++)
        #pragma unroll
        for (int j = 0; j < 4; j++)
            #pragma unroll
            for (int q = 0; q < 4; q++) acc[i][j][q] = 0.f;

    float4 pa0, pa1, pb0, pb1;
    #define LOADT(kt) do { \
        pa0 = *(const float4*)(Ab + (size_t)ar * K + (kt)*16 + ac); \
        pa1 = *(const float4*)(Ab + (size_t)(ar + 64) * K + (kt)*16 + ac); \
        pb0 = *(const float4*)(Bbp + (size_t)((kt)*16 + br) * N + bc); \
        pb1 = *(const float4*)(Bbp + (size_t)((kt)*16 + br + 8) * N + bc); \
    } while (0)
    #define STORET() do { \
        *(float4*)(As + ar * LDA + ac) = make_float4(tf32r(pa0.x), tf32r(pa0.y), tf32r(pa0.z), tf32r(pa0.w)); \
        *(float4*)(As + (ar + 64) * LDA + ac) = make_float4(tf32r(pa1.x), tf32r(pa1.y), tf32r(pa1.z), tf32r(pa1.w)); \
        *(float4*)(Bs + br * LDB + bc) = make_float4(tf32r(pb0.x), tf32r(pb0.y), tf32r(pb0.z), tf32r(pb0.w)); \
        *(float4*)(Bs + (br + 8) * LDB + bc) = make_float4(tf32r(pb1.x), tf32r(pb1.y), tf32r(pb1.z), tf32r(pb1.w)); \
    } while (0)

    const int NT = K >> 4;
    LOADT(0);
    STORET();
    __syncthreads();

    for (int kt = 0; kt < NT; kt++) {
        if (kt + 1 < NT) LOADT(kt + 1);
        #pragma unroll
        for (int kk = 0; kk < 16; kk += 8) {
            uint32_t af[4][4], bf[4][2];
            #pragma unroll
            for (int mt = 0; mt < 4; mt++) {
                int r0 = warpM * 64 + mt * 16 + lr;
                af[mt][0] = fbits(As[r0 * LDA + kk + lc]);
                af[mt][1] = fbits(As[(r0 + 8) * LDA + kk + lc]);
                af[mt][2] = fbits(As[r0 * LDA + kk + 4 + lc]);
                af[mt][3] = fbits(As[(r0 + 8) * LDA + kk + 4 + lc]);
            }
            #pragma unroll
            for (int nt = 0; nt < 4; nt++) {
                int c0 = warpN * 32 + nt * 8 + lr;
                bf[nt][0] = fbits(Bs[(kk + lc) * LDB + c0]);
                bf[nt][1] = fbits(Bs[(kk + 4 + lc) * LDB + c0]);
            }
            #pragma unroll
            for (int mt = 0; mt < 4; mt++)
                #pragma unroll
                for (int nt = 0; nt < 4; nt++)
                    mma_tf32(acc[mt][nt], af[mt], bf[nt]);
        }
        __syncthreads();
        if (kt + 1 < NT) {
            STORET();
            __syncthreads();
        }
    }

    #pragma unroll
    for (int mt = 0; mt < 4; mt++)
        #pragma unroll
        for (int nt = 0; nt < 4; nt++) {
            int row = brow + warpM * 64 + mt * 16 + lr;
            int col = bcol + warpN * 32 + nt * 8 + 2 * lc;
            *(float2*)&C[(size_t)row * N + col] = make_float2(acc[mt][nt][0], acc[mt][nt][1]);
            *(float2*)&C[(size_t)(row + 8) * N + col] = make_float2(acc[mt][nt][2], acc[mt][nt][3]);
        }
    #undef LOADT
    #undef STORET
}

// ---------------------------------------------------------------------------
// Causal flash attention, tf32 tensor-core. 64 queries/block, 64 keys/iter.
// 256 threads, warp grid 2x4 (warp tile 32x16 for both S and O).
// ---------------------------------------------------------------------------
#define LDF 72   // 64 + 8: all frag loads conflict-free ((8x+y)%32 unique)

__global__ __launch_bounds__(256)
void flash_tf32(const float* __restrict__ qkv, float* __restrict__ out)
{
    extern __shared__ float sm[];
    float* Qs  = sm;               // 64*LDF
    float* Ks  = Qs + 64 * LDF;
    float* Vs  = Ks + 64 * LDF;
    float* Ss  = Vs + 64 * LDF;
    float* m_s = Ss + 64 * LDF;    // 64
    float* l_s = m_s + 64;
    float* a_s = l_s + 64;

    const int qblk = (int)gridDim.x - 1 - (int)blockIdx.x;  // heavy blocks first
    const int h = blockIdx.y, b = blockIdx.z;
    const int tid = threadIdx.x;
    const int lane = tid & 31, wid = tid >> 5;
    const int warpM = wid >> 2, warpN = wid & 3;
    const int lr = lane >> 2, lc = lane & 3;
    const float NEG = -1e30f;
    const float scale = 0.125f;

    const size_t qrow0 = (size_t)(b * Tt + qblk * 64);
    const float* qbase = qkv + qrow0 * C3 + h * HSs;

    // Load Q tile (resident, tf32-rounded)
    #pragma unroll
    for (int it = 0; it < 4; it++) {
        int idx = tid + it * 256;
        int r = idx >> 4, c4 = (idx & 15) << 2;
        float4 v = *(const float4*)(qbase + (size_t)r * C3 + c4);
        *(float4*)(Qs + r * LDF + c4) =
            make_float4(tf32r(v.x), tf32r(v.y), tf32r(v.z), tf32r(v.w));
    }
    if (tid < 64) { m_s[tid] = NEG; l_s[tid] = 0.f; }

    float accO[2][2][4];
    #pragma unroll
    for (int i = 0; i < 2; i++)
        #pragma unroll
        for (int j = 0; j < 2; j++)
            #pragma unroll
            for (int q = 0; q < 4; q++) accO[i][j][q] = 0.f;

    for (int jb = 0; jb <= qblk; jb++) {
        __syncthreads();   // prior iter's Ks/Vs/Ss reads complete
        const float* kbase = qkv + (size_t)(b * Tt + jb * 64) * C3 + Cc + h * HSs;
        const float* vbase = kbase + Cc;
        #pragma unroll
        for (int it = 0; it < 4; it++) {
            int idx = tid + it * 256;
            int r = idx >> 4, c4 = (idx & 15) << 2;
            float4 kv = *(const float4*)(kbase + (size_t)r * C3 + c4);
            *(float4*)(Ks + r * LDF + c4) =
                make_float4(tf32r(kv.x), tf32r(kv.y), tf32r(kv.z), tf32r(kv.w));
            float4 vv = *(const float4*)(vbase + (size_t)r * C3 + c4);
            *(float4*)(Vs + r * LDF + c4) =
                make_float4(tf32r(vv.x), tf32r(vv.y), tf32r(vv.z), tf32r(vv.w));
        }
        __syncthreads();

        // ---- S = Q * K^T (tf32 mma) ----
        float sAcc[2][2][4];
        #pragma unroll
        for (int i = 0; i < 2; i++)
            #pragma unroll
            for (int j = 0; j < 2; j++)
                #pragma unroll
                for (int q = 0; q < 4; q++) sAcc[i][j][q] = 0.f;

        #pragma unroll
        for (int k0 = 0; k0 < 64; k0 += 8) {
            uint32_t af[2][4], bf[2][2];
            #pragma unroll
            for (int mt = 0; mt < 2; mt++) {
                int r0 = warpM * 32 + mt * 16 + lr;
                af[mt][0] = fbits(Qs[r0 * LDF + k0 + lc]);
                af[mt][1] = fbits(Qs[(r0 + 8) * LDF + k0 + lc]);
                af[mt][2] = fbits(Qs[r0 * LDF + k0 + 4 + lc]);
                af[mt][3] = fbits(Qs[(r0 + 8) * LDF + k0 + 4 + lc]);
            }
            #pragma unroll
            for (int nt = 0; nt < 2; nt++) {
                int n0 = warpN * 16 + nt * 8 + lr;   // key index
                bf[nt][0] = fbits(Ks[n0 * LDF + k0 + lc]);
                bf[nt][1] = fbits(Ks[n0 * LDF + k0 + 4 + lc]);
            }
            #pragma unroll
            for (int mt = 0; mt < 2; mt++)
                #pragma unroll
                for (int nt = 0; nt < 2; nt++)
                    mma_tf32(sAcc[mt][nt], af[mt], bf[nt]);
        }

        // scale + causal mask + store S to smem
        const bool diag = (jb == qblk);
        #pragma unroll
        for (int mt = 0; mt < 2; mt++)
            #pragma unroll
            for (int nt = 0; nt < 2; nt++) {
                int row0 = warpM * 32 + mt * 16 + lr;
                int col = warpN * 16 + nt * 8 + 2 * lc;
                #pragma unroll
                for (int half = 0; half < 2; half++) {
                    int row = row0 + half * 8;
                    float s0 = sAcc[mt][nt][half * 2 + 0] * scale;
                    float s1 = sAcc[mt][nt][half * 2 + 1] * scale;
                    if (diag) {
                        if (col > row) s0 = NEG;
                        if (col + 1 > row) s1 = NEG;
                    }
                    *(float2*)(Ss + row * LDF + col) = make_float2(s0, s1);
                }
            }
        __syncthreads();

        // ---- online softmax (4 threads per row, 16 cols each) ----
        {
            int r = tid >> 2, p = tid & 3;
            float* row = Ss + r * LDF + p * 16;
            float mx = NEG;
            #pragma unroll
            for (int c = 0; c < 16; c++) mx = fmaxf(mx, row[c]);
            mx = fmaxf(mx, __shfl_xor_sync(0xffffffffu, mx, 1));
            mx = fmaxf(mx, __shfl_xor_sync(0xffffffffu, mx, 2));
            float m_old = m_s[r];
            float m_new = fmaxf(m_old, mx);
            float sum = 0.f;
            #pragma unroll
            for (int c = 0; c < 16; c++) {
                float e = __expf(row[c] - m_new);
                row[c] = tf32r(e);
                sum += e;
            }
            sum += __shfl_xor_sync(0xffffffffu, sum, 1);
            sum += __shfl_xor_sync(0xffffffffu, sum, 2);
            if (p == 0) {
                float alpha = __expf(m_old - m_new);
                m_s[r] = m_new;
                l_s[r] = l_s[r] * alpha + sum;
                a_s[r] = alpha;
            }
        }
        __syncthreads();

        // ---- rescale O, then O += P * V (tf32 mma) ----
        #pragma unroll
        for (int mt = 0; mt < 2; mt++) {
            int r0 = warpM * 32 + mt * 16 + lr;
            float al0 = a_s[r0], al1 = a_s[r0 + 8];
            #pragma unroll
            for (int nt = 0; nt < 2; nt++) {
                accO[mt][nt][0] *= al0; accO[mt][nt][1] *= al0;
                accO[mt][nt][2] *= al1; accO[mt][nt][3] *= al1;
            }
        }
        #pragma unroll
        for (int k0 = 0; k0 < 64; k0 += 8) {
            uint32_t af[2][4], bf[2][2];
            #pragma unroll
            for (int mt = 0; mt < 2; mt++) {
                int r0 = warpM * 32 + mt * 16 + lr;
                af[mt][0] = fbits(Ss[r0 * LDF + k0 + lc]);
                af[mt][1] = fbits(Ss[(r0 + 8) * LDF + k0 + lc]);
                af[mt][2] = fbits(Ss[r0 * LDF + k0 + 4 + lc]);
                af[mt][3] = fbits(Ss[(r0 + 8) * LDF + k0 + 4 + lc]);
            }
            #pragma unroll
            for (int nt = 0; nt < 2; nt++) {
                int c0 = warpN * 16 + nt * 8 + lr;   // d index
                bf[nt][0] = fbits(Vs[(k0 + lc) * LDF + c0]);
                bf[nt][1] = fbits(Vs[(k0 + 4 + lc) * LDF + c0]);
            }
            #pragma unroll
            for (int mt = 0; mt < 2; mt++)
                #pragma unroll
                for (int nt = 0; nt < 2; nt++)
                    mma_tf32(accO[mt][nt], af[mt], bf[nt]);
        }
    }

    __syncthreads();
    // normalize + write O to [B*T, C] layout
    float* obase = out + qrow0 * Cc + h * HSs;
    #pragma unroll
    for (int mt = 0; mt < 2; mt++) {
        int r0 = warpM * 32 + mt * 16 + lr;
        float rl0 = 1.f / l_s[r0];
        float rl1 = 1.f / l_s[r0 + 8];
        #pragma unroll
        for (int nt = 0; nt < 2; nt++) {
            int col = warpN * 16 + nt * 8 + 2 * lc;
            *(float2*)(obase + (size_t)r0 * Cc + col) =
                make_float2(accO[mt][nt][0] * rl0, accO[mt][nt][1] * rl0);
            *(float2*)(obase + (size_t)(r0 + 8) * Cc + col) =
                make_float2(accO[mt][nt][2] * rl1, accO[mt][nt][3] * rl1);
        }
    }
}

// ---------------------------------------------------------------------------
extern "C" void kernel_launch(void* const* d_in, const int* in_sizes, int n_in,
                              void* d_out, int out_size)
{
    const float* x      = (const float*)d_in[0];   // [B,T,C]
    const float* w_attn = (const float*)d_in[1];   // [C,3C]
    const float* w_proj = (const float*)d_in[2];   // [C,C]
    float* out = (float*)d_out;                    // [B,T,C]

    float *qkv, *att;
    cudaGetSymbolAddress((void**)&qkv, g_qkv);
    cudaGetSymbolAddress((void**)&att, g_att);

    const size_t FLASH_SMEM = (size_t)(4 * 64 * LDF + 3 * 64) * sizeof(float);
    cudaFuncSetAttribute(flash_tf32, cudaFuncAttributeMaxDynamicSharedMemorySize,
                         (int)FLASH_SMEM);

    // 1) QKV projection: [8192,768] @ [768,2304]
    gemm_tf32<<<dim3(C3 / 128, BT / 128), 256>>>(x, w_attn, qkv, BT, C3, Cc);
    // 2) Causal flash attention (tf32 tensor cores)
    flash_tf32<<<dim3(Tt / 64, NHh, Bb), 256, FLASH_SMEM>>>(qkv, att);
    // 3) Output projection: [8192,768] @ [768,768]
    gemm_tf32<<<dim3(Cc / 128, BT / 128), 256>>>(att, w_proj, out, BT, Cc, Cc);
}

// round 3
// speedup vs baseline: 3.2645x; 1.3480x over previous
#include <cuda_runtime.h>
#include <math.h>
#include <stdint.h>

#define Bb 2
#define Tt 4096
#define Cc 768
#define NHh 12
#define HSs 64
#define BT (Bb*Tt)
#define C3 (3*Cc)

__device__ float g_qkv[(size_t)BT * C3];   // [B*T, 3C]
__device__ float g_att[(size_t)BT * Cc];   // [B*T, C]

__device__ __forceinline__ float tf32r(float x) {
    uint32_t u;
    asm("cvt.rna.tf32.f32 %0, %1;" : "=r"(u) : "f"(x));
    return __uint_as_float(u);
}
__device__ __forceinline__ uint32_t fbits(float x) { return __float_as_uint(x); }

__device__ __forceinline__ void mma_tf32(float c[4], const uint32_t a[4], const uint32_t b[2]) {
    asm volatile(
        "mma.sync.aligned.m16n8k8.row.col.f32.tf32.tf32.f32 "
        "{%0,%1,%2,%3},{%4,%5,%6,%7},{%8,%9},{%0,%1,%2,%3};"
        : "+f"(c[0]), "+f"(c[1]), "+f"(c[2]), "+f"(c[3])
        : "r"(a[0]), "r"(a[1]), "r"(a[2]), "r"(a[3]), "r"(b[0]), "r"(b[1]));
}

// ---------------------------------------------------------------------------
// TF32 GEMM (unchanged from R2): C[M,N] = A[M,K]*B[K,N], row-major.
// ---------------------------------------------------------------------------
#define LDA 20
#define LDB 136

__global__ __launch_bounds__(256, 2)
void gemm_tf32(const float* __restrict__ A, const float* __restrict__ B,
               float* __restrict__ C, int M, int N, int K)
{
    __shared__ float As[128 * LDA];
    __shared__ float Bs[16 * LDB];

    const int tid = threadIdx.x;
    const int lane = tid & 31, wid = tid >> 5;
    const int warpM = wid >> 2, warpN = wid & 3;
    const int lr = lane >> 2, lc = lane & 3;
    const int brow = blockIdx.y << 7, bcol = blockIdx.x << 7;

    const int ar = tid >> 2;
    const int ac = (tid & 3) << 2;
    const int br = tid >> 5;
    const int bc = lane << 2;

    const float* Ab = A + (size_t)brow * K;
    const float* Bbp = B + bcol;

    float acc[4][4][4];
    #pragma unroll
    for (int i = 0; i < 4; i++)
        #pragma unroll
        for (int j = 0; j < 4; j++)
            #pragma unroll
            for (int q = 0; q < 4; q++) acc[i][j][q] = 0.f;

    float4 pa0, pa1, pb0, pb1;
    #define LOADT(kt) do { \
        pa0 = *(const float4*)(Ab + (size_t)ar * K + (kt)*16 + ac); \
        pa1 = *(const float4*)(Ab + (size_t)(ar + 64) * K + (kt)*16 + ac); \
        pb0 = *(const float4*)(Bbp + (size_t)((kt)*16 + br) * N + bc); \
        pb1 = *(const float4*)(Bbp + (size_t)((kt)*16 + br + 8) * N + bc); \
    } while (0)
    #define STORET() do { \
        *(float4*)(As + ar * LDA + ac) = make_float4(tf32r(pa0.x), tf32r(pa0.y), tf32r(pa0.z), tf32r(pa0.w)); \
        *(float4*)(As + (ar + 64) * LDA + ac) = make_float4(tf32r(pa1.x), tf32r(pa1.y), tf32r(pa1.z), tf32r(pa1.w)); \
        *(float4*)(Bs + br * LDB + bc) = make_float4(tf32r(pb0.x), tf32r(pb0.y), tf32r(pb0.z), tf32r(pb0.w)); \
        *(float4*)(Bs + (br + 8) * LDB + bc) = make_float4(tf32r(pb1.x), tf32r(pb1.y), tf32r(pb1.z), tf32r(pb1.w)); \
    } while (0)

    const int NT = K >> 4;
    LOADT(0);
    STORET();
    __syncthreads();

    for (int kt = 0; kt < NT; kt++) {
        if (kt + 1 < NT) LOADT(kt + 1);
        #pragma unroll
        for (int kk = 0; kk < 16; kk += 8) {
            uint32_t af[4][4], bf[4][2];
            #pragma unroll
            for (int mt = 0; mt < 4; mt++) {
                int r0 = warpM * 64 + mt * 16 + lr;
                af[mt][0] = fbits(As[r0 * LDA + kk + lc]);
                af[mt][1] = fbits(As[(r0 + 8) * LDA + kk + lc]);
                af[mt][2] = fbits(As[r0 * LDA + kk + 4 + lc]);
                af[mt][3] = fbits(As[(r0 + 8) * LDA + kk + 4 + lc]);
            }
            #pragma unroll
            for (int nt = 0; nt < 4; nt++) {
                int c0 = warpN * 32 + nt * 8 + lr;
                bf[nt][0] = fbits(Bs[(kk + lc) * LDB + c0]);
                bf[nt][1] = fbits(Bs[(kk + 4 + lc) * LDB + c0]);
            }
            #pragma unroll
            for (int mt = 0; mt < 4; mt++)
                #pragma unroll
                for (int nt = 0; nt < 4; nt++)
                    mma_tf32(acc[mt][nt], af[mt], bf[nt]);
        }
        __syncthreads();
        if (kt + 1 < NT) {
            STORET();
            __syncthreads();
        }
    }

    #pragma unroll
    for (int mt = 0; mt < 4; mt++)
        #pragma unroll
        for (int nt = 0; nt < 4; nt++) {
            int row = brow + warpM * 64 + mt * 16 + lr;
            int col = bcol + warpN * 32 + nt * 8 + 2 * lc;
            *(float2*)&C[(size_t)row * N + col] = make_float2(acc[mt][nt][0], acc[mt][nt][1]);
            *(float2*)&C[(size_t)(row + 8) * N + col] = make_float2(acc[mt][nt][2], acc[mt][nt][3]);
        }
    #undef LOADT
    #undef STORET
}

// ---------------------------------------------------------------------------
// Causal flash attention, tf32, register softmax.
// 128 queries/block, 64 keys/iter, 8 warps; warp owns 16 q-rows x 64 key cols.
// Q resident in registers as A-frags (pre-scaled). Softmax + P-layout
// conversion entirely in registers/shfl. 2 syncthreads per key iteration.
// ---------------------------------------------------------------------------
#define LDF 72

__global__ __launch_bounds__(256, 2)
void flash_tf32(const float* __restrict__ qkv, float* __restrict__ out)
{
    extern __shared__ float sm[];
    float* Qstage = sm;            // 128*LDF (overlaps Ks+Vs)
    float* Ks = sm;                // 64*LDF
    float* Vs = sm + 64 * LDF;     // 64*LDF

    const int qt = (int)gridDim.x - 1 - (int)blockIdx.x;  // heavy first
    const int h = blockIdx.y, b = blockIdx.z;
    const int tid = threadIdx.x;
    const int lane = tid & 31, w = tid >> 5;
    const int lr = lane >> 2, lc = lane & 3;
    const float NEG = -1e30f;
    const float scale = 0.125f;

    const int q0 = qt * 128;
    const size_t qrow0 = (size_t)(b * Tt + q0);
    const float* qbase = qkv + qrow0 * C3 + h * HSs;

    // Stage Q (scaled + tf32-rounded) into smem, then pull A-frags to regs
    #pragma unroll
    for (int it = 0; it < 8; it++) {
        int idx = tid + it * 256;            // 0..2047
        int r = idx >> 4, c4 = (idx & 15) << 2;
        float4 v = *(const float4*)(qbase + (size_t)r * C3 + c4);
        *(float4*)(Qstage + r * LDF + c4) =
            make_float4(tf32r(v.x * scale), tf32r(v.y * scale),
                        tf32r(v.z * scale), tf32r(v.w * scale));
    }
    __syncthreads();

    uint32_t qf[8][4];
    {
        int r0 = w * 16 + lr;
        #pragma unroll
        for (int j = 0; j < 8; j++) {
            qf[j][0] = fbits(Qstage[r0 * LDF + 8 * j + lc]);
            qf[j][1] = fbits(Qstage[(r0 + 8) * LDF + 8 * j + lc]);
            qf[j][2] = fbits(Qstage[r0 * LDF + 8 * j + 4 + lc]);
            qf[j][3] = fbits(Qstage[(r0 + 8) * LDF + 8 * j + 4 + lc]);
        }
    }

    float accO[8][4];
    #pragma unroll
    for (int j = 0; j < 8; j++)
        #pragma unroll
        for (int q = 0; q < 4; q++) accO[j][q] = 0.f;
    float m0 = NEG, m1 = NEG, l0 = 0.f, l1 = 0.f;

    const int rowA = q0 + w * 16 + lr;       // rows for c0/c1
    const int rowB = rowA + 8;               // rows for c2/c3
    const int nIter = 2 * qt + 2;

    for (int jb = 0; jb < nIter; jb++) {
        __syncthreads();   // Q-frag reads done (jb=0) / prior V-frag reads done
        const float* kbase = qkv + (size_t)(b * Tt + jb * 64) * C3 + Cc + h * HSs;
        const float* vbase = kbase + Cc;
        #pragma unroll
        for (int it = 0; it < 4; it++) {
            int idx = tid + it * 256;
            int r = idx >> 4, c4 = (idx & 15) << 2;
            float4 kv = *(const float4*)(kbase + (size_t)r * C3 + c4);
            *(float4*)(Ks + r * LDF + c4) =
                make_float4(tf32r(kv.x), tf32r(kv.y), tf32r(kv.z), tf32r(kv.w));
            float4 vv = *(const float4*)(vbase + (size_t)r * C3 + c4);
            *(float4*)(Vs + r * LDF + c4) =
                make_float4(tf32r(vv.x), tf32r(vv.y), tf32r(vv.z), tf32r(vv.w));
        }
        __syncthreads();

        // ---- S = Qf x K^T ----  (warp: 16 x 64)
        float sAcc[8][4];
        #pragma unroll
        for (int j = 0; j < 8; j++)
            #pragma unroll
            for (int q = 0; q < 4; q++) sAcc[j][q] = 0.f;

        #pragma unroll
        for (int ks = 0; ks < 8; ks++) {
            #pragma unroll
            for (int nj = 0; nj < 8; nj++) {
                uint32_t bf[2];
                int n0 = nj * 8 + lr;
                bf[0] = fbits(Ks[n0 * LDF + ks * 8 + lc]);
                bf[1] = fbits(Ks[n0 * LDF + ks * 8 + 4 + lc]);
                mma_tf32(sAcc[nj], qf[ks], bf);
            }
        }

        // ---- causal mask (only near-diagonal tiles need it) ----
        if (jb * 64 + 63 > q0 + w * 16) {
            #pragma unroll
            for (int nj = 0; nj < 8; nj++) {
                int col = jb * 64 + nj * 8 + 2 * lc;
                if (col > rowA)     sAcc[nj][0] = NEG;
                if (col + 1 > rowA) sAcc[nj][1] = NEG;
                if (col > rowB)     sAcc[nj][2] = NEG;
                if (col + 1 > rowB) sAcc[nj][3] = NEG;
            }
        }

        // ---- online softmax, all registers ----
        float mxA = NEG, mxB = NEG;
        #pragma unroll
        for (int nj = 0; nj < 8; nj++) {
            mxA = fmaxf(mxA, fmaxf(sAcc[nj][0], sAcc[nj][1]));
            mxB = fmaxf(mxB, fmaxf(sAcc[nj][2], sAcc[nj][3]));
        }
        mxA = fmaxf(mxA, __shfl_xor_sync(0xffffffffu, mxA, 1));
        mxA = fmaxf(mxA, __shfl_xor_sync(0xffffffffu, mxA, 2));
        mxB = fmaxf(mxB, __shfl_xor_sync(0xffffffffu, mxB, 1));
        mxB = fmaxf(mxB, __shfl_xor_sync(0xffffffffu, mxB, 2));

        float mn0 = fmaxf(m0, mxA), mn1 = fmaxf(m1, mxB);
        float al0 = __expf(m0 - mn0), al1 = __expf(m1 - mn1);
        m0 = mn0; m1 = mn1;

        float sumA = 0.f, sumB = 0.f;
        #pragma unroll
        for (int nj = 0; nj < 8; nj++) {
            float e0 = __expf(sAcc[nj][0] - mn0);
            float e1 = __expf(sAcc[nj][1] - mn0);
            float e2 = __expf(sAcc[nj][2] - mn1);
            float e3 = __expf(sAcc[nj][3] - mn1);
            sumA += e0 + e1; sumB += e2 + e3;
            sAcc[nj][0] = tf32r(e0); sAcc[nj][1] = tf32r(e1);
            sAcc[nj][2] = tf32r(e2); sAcc[nj][3] = tf32r(e3);
        }
        sumA += __shfl_xor_sync(0xffffffffu, sumA, 1);
        sumA += __shfl_xor_sync(0xffffffffu, sumA, 2);
        sumB += __shfl_xor_sync(0xffffffffu, sumB, 1);
        sumB += __shfl_xor_sync(0xffffffffu, sumB, 2);
        l0 = l0 * al0 + sumA;
        l1 = l1 * al1 + sumB;

        // rescale O
        #pragma unroll
        for (int nj = 0; nj < 8; nj++) {
            accO[nj][0] *= al0; accO[nj][1] *= al0;
            accO[nj][2] *= al1; accO[nj][3] *= al1;
        }

        // ---- convert P from C-layout to A-frag layout via shfl; PV mma ----
        const int s1 = (lane & 28) | (lc >> 1);
        const int s2 = s1 + 2;
        const bool odd = lc & 1;
        #pragma unroll
        for (int ks = 0; ks < 8; ks++) {
            float c0 = sAcc[ks][0], c1 = sAcc[ks][1];
            float c2 = sAcc[ks][2], c3 = sAcc[ks][3];
            float t0 = __shfl_sync(0xffffffffu, c0, s1);
            float t1 = __shfl_sync(0xffffffffu, c1, s1);
            float u0 = __shfl_sync(0xffffffffu, c2, s1);
            float u1 = __shfl_sync(0xffffffffu, c3, s1);
            float v0 = __shfl_sync(0xffffffffu, c0, s2);
            float v1 = __shfl_sync(0xffffffffu, c1, s2);
            float w0 = __shfl_sync(0xffffffffu, c2, s2);
            float w1 = __shfl_sync(0xffffffffu, c3, s2);
            uint32_t af[4];
            af[0] = fbits(odd ? t1 : t0);
            af[1] = fbits(odd ? u1 : u0);
            af[2] = fbits(odd ? v1 : v0);
            af[3] = fbits(odd ? w1 : w0);
            #pragma unroll
            for (int nj = 0; nj < 8; nj++) {
                uint32_t bf[2];
                int c0i = nj * 8 + lr;
                bf[0] = fbits(Vs[(ks * 8 + lc) * LDF + c0i]);
                bf[1] = fbits(Vs[(ks * 8 + 4 + lc) * LDF + c0i]);
                mma_tf32(accO[nj], af, bf);
            }
        }
    }

    // ---- normalize + write O ----
    float rl0 = 1.f / l0, rl1 = 1.f / l1;
    float* obase = out + qrow0 * Cc + h * HSs;
    int r0 = w * 16 + lr;
    #pragma unroll
    for (int nj = 0; nj < 8; nj++) {
        int col = nj * 8 + 2 * lc;
        *(float2*)(obase + (size_t)r0 * Cc + col) =
            make_float2(accO[nj][0] * rl0, accO[nj][1] * rl0);
        *(float2*)(obase + (size_t)(r0 + 8) * Cc + col) =
            make_float2(accO[nj][2] * rl1, accO[nj][3] * rl1);
    }
}

// ---------------------------------------------------------------------------
extern "C" void kernel_launch(void* const* d_in, const int* in_sizes, int n_in,
                              void* d_out, int out_size)
{
    const float* x      = (const float*)d_in[0];
    const float* w_attn = (const float*)d_in[1];
    const float* w_proj = (const float*)d_in[2];
    float* out = (float*)d_out;

    float *qkv, *att;
    cudaGetSymbolAddress((void**)&qkv, g_qkv);
    cudaGetSymbolAddress((void**)&att, g_att);

    const size_t FLASH_SMEM = (size_t)(128 * LDF) * sizeof(float);  // 36864 B
    cudaFuncSetAttribute(flash_tf32, cudaFuncAttributeMaxDynamicSharedMemorySize,
                         (int)FLASH_SMEM);

    gemm_tf32<<<dim3(C3 / 128, BT / 128), 256>>>(x, w_attn, qkv, BT, C3, Cc);
    flash_tf32<<<dim3(Tt / 128, NHh, Bb), 256, FLASH_SMEM>>>(qkv, att);
    gemm_tf32<<<dim3(Cc / 128, BT / 128), 256>>>(att, w_proj, out, BT, Cc, Cc);
}

// round 4
// speedup vs baseline: 3.2792x; 1.0045x over previous
#include <cuda_runtime.h>
#include <math.h>
#include <stdint.h>

#define Bb 2
#define Tt 4096
#define Cc 768
#define NHh 12
#define HSs 64
#define BT (Bb*Tt)
#define C3 (3*Cc)

__device__ float g_qkv[(size_t)BT * C3];   // [B*T, 3C]
__device__ float g_att[(size_t)BT * Cc];   // [B*T, C]

__device__ __forceinline__ float tf32r(float x) {
    uint32_t u;
    asm("cvt.rna.tf32.f32 %0, %1;" : "=r"(u) : "f"(x));
    return __uint_as_float(u);
}
__device__ __forceinline__ uint32_t fbits(float x) { return __float_as_uint(x); }
__device__ __forceinline__ float ex2(float x) {
    float r;
    asm("ex2.approx.ftz.f32 %0, %1;" : "=f"(r) : "f"(x));
    return r;
}
__device__ __forceinline__ void cp16(uint32_t dst, const void* src) {
    asm volatile("cp.async.cg.shared.global [%0], [%1], 16;" :: "r"(dst), "l"(src));
}
__device__ __forceinline__ void cp_commit() { asm volatile("cp.async.commit_group;"); }
__device__ __forceinline__ void cp_wait1()  { asm volatile("cp.async.wait_group 1;"); }

__device__ __forceinline__ void mma_tf32(float c[4], const uint32_t a[4], const uint32_t b[2]) {
    asm volatile(
        "mma.sync.aligned.m16n8k8.row.col.f32.tf32.tf32.f32 "
        "{%0,%1,%2,%3},{%4,%5,%6,%7},{%8,%9},{%0,%1,%2,%3};"
        : "+f"(c[0]), "+f"(c[1]), "+f"(c[2]), "+f"(c[3])
        : "r"(a[0]), "r"(a[1]), "r"(a[2]), "r"(a[3]), "r"(b[0]), "r"(b[1]));
}

// ---------------------------------------------------------------------------
// TF32 GEMM, double-buffered smem (1 sync per k-chunk of 16).
// ---------------------------------------------------------------------------
#define LDA 20
#define LDB 136

__global__ __launch_bounds__(256, 2)
void gemm_tf32(const float* __restrict__ A, const float* __restrict__ B,
               float* __restrict__ C, int M, int N, int K)
{
    __shared__ float As[2][128 * LDA];
    __shared__ float Bs[2][16 * LDB];

    const int tid = threadIdx.x;
    const int lane = tid & 31, wid = tid >> 5;
    const int warpM = wid >> 2, warpN = wid & 3;
    const int lr = lane >> 2, lc = lane & 3;
    const int brow = blockIdx.y << 7, bcol = blockIdx.x << 7;

    const int ar = tid >> 2;
    const int ac = (tid & 3) << 2;
    const int br = tid >> 5;
    const int bc = lane << 2;

    const float* Ab = A + (size_t)brow * K;
    const float* Bbp = B + bcol;

    float acc[4][4][4];
    #pragma unroll
    for (int i = 0; i < 4; i++)
        #pragma unroll
        for (int j = 0; j < 4; j++)
            #pragma unroll
            for (int q = 0; q < 4; q++) acc[i][j][q] = 0.f;

    float4 pa0, pa1, pb0, pb1;
    #define LOADT(kt) do { \
        pa0 = *(const float4*)(Ab + (size_t)ar * K + (kt)*16 + ac); \
        pa1 = *(const float4*)(Ab + (size_t)(ar + 64) * K + (kt)*16 + ac); \
        pb0 = *(const float4*)(Bbp + (size_t)((kt)*16 + br) * N + bc); \
        pb1 = *(const float4*)(Bbp + (size_t)((kt)*16 + br + 8) * N + bc); \
    } while (0)
    #define STORET(s) do { \
        *(float4*)(As[s] + ar * LDA + ac) = make_float4(tf32r(pa0.x), tf32r(pa0.y), tf32r(pa0.z), tf32r(pa0.w)); \
        *(float4*)(As[s] + (ar + 64) * LDA + ac) = make_float4(tf32r(pa1.x), tf32r(pa1.y), tf32r(pa1.z), tf32r(pa1.w)); \
        *(float4*)(Bs[s] + br * LDB + bc) = make_float4(tf32r(pb0.x), tf32r(pb0.y), tf32r(pb0.z), tf32r(pb0.w)); \
        *(float4*)(Bs[s] + (br + 8) * LDB + bc) = make_float4(tf32r(pb1.x), tf32r(pb1.y), tf32r(pb1.z), tf32r(pb1.w)); \
    } while (0)

    const int NT = K >> 4;
    LOADT(0);
    STORET(0);
    __syncthreads();

    for (int kt = 0; kt < NT; kt++) {
        const int cur = kt & 1;
        if (kt + 1 < NT) LOADT(kt + 1);
        const float* Ac = As[cur];
        const float* Bc = Bs[cur];
        #pragma unroll
        for (int kk = 0; kk < 16; kk += 8) {
            uint32_t af[4][4], bf[4][2];
            #pragma unroll
            for (int mt = 0; mt < 4; mt++) {
                int r0 = warpM * 64 + mt * 16 + lr;
                af[mt][0] = fbits(Ac[r0 * LDA + kk + lc]);
                af[mt][1] = fbits(Ac[(r0 + 8) * LDA + kk + lc]);
                af[mt][2] = fbits(Ac[r0 * LDA + kk + 4 + lc]);
                af[mt][3] = fbits(Ac[(r0 + 8) * LDA + kk + 4 + lc]);
            }
            #pragma unroll
            for (int nt = 0; nt < 4; nt++) {
                int c0 = warpN * 32 + nt * 8 + lr;
                bf[nt][0] = fbits(Bc[(kk + lc) * LDB + c0]);
                bf[nt][1] = fbits(Bc[(kk + 4 + lc) * LDB + c0]);
            }
            #pragma unroll
            for (int mt = 0; mt < 4; mt++)
                #pragma unroll
                for (int nt = 0; nt < 4; nt++)
                    mma_tf32(acc[mt][nt], af[mt], bf[nt]);
        }
        if (kt + 1 < NT) STORET((kt + 1) & 1);
        __syncthreads();
    }

    #pragma unroll
    for (int mt = 0; mt < 4; mt++)
        #pragma unroll
        for (int nt = 0; nt < 4; nt++) {
            int row = brow + warpM * 64 + mt * 16 + lr;
            int col = bcol + warpN * 32 + nt * 8 + 2 * lc;
            *(float2*)&C[(size_t)row * N + col] = make_float2(acc[mt][nt][0], acc[mt][nt][1]);
            *(float2*)&C[(size_t)(row + 8) * N + col] = make_float2(acc[mt][nt][2], acc[mt][nt][3]);
        }
    #undef LOADT
    #undef STORET
}

// ---------------------------------------------------------------------------
// Causal flash attention, tf32, register softmax, cp.async double-buffered K/V.
// 128 q/block, 64 keys/iter, 8 warps (16 q-rows x 64 keys each).
// Base-2 softmax (log2e folded into Q scale). K tile rna-converted in place;
// V consumed raw (HW tf32 truncation).
// ---------------------------------------------------------------------------
#define LDF 72
#define BUFF (64 * LDF)          // one 64x64 tile (padded)

__global__ __launch_bounds__(256, 2)
void flash_tf32(const float* __restrict__ qkv, float* __restrict__ out)
{
    extern __shared__ float sm[];
    // buffers: [Ks0 | Vs0 | Ks1 | Vs1]; Q staging overlaps Ks0+Vs0
    float* Qstage = sm;

    const int qt = (int)gridDim.x - 1 - (int)blockIdx.x;  // heavy first
    const int h = blockIdx.y, b = blockIdx.z;
    const int tid = threadIdx.x;
    const int lane = tid & 31, w = tid >> 5;
    const int lr = lane >> 2, lc = lane & 3;
    const float NEG = -1e30f;
    const float qscale = 0.125f * 1.44269504089f;   // 1/sqrt(64) * log2(e)

    const int q0 = qt * 128;
    const size_t qrow0 = (size_t)(b * Tt + q0);
    const float* qbase = qkv + qrow0 * C3 + h * HSs;

    // ---- stage Q (scaled + rna) and pull A-frags into registers ----
    #pragma unroll
    for (int it = 0; it < 8; it++) {
        int idx = tid + it * 256;
        int r = idx >> 4, c4 = (idx & 15) << 2;
        float4 v = *(const float4*)(qbase + (size_t)r * C3 + c4);
        *(float4*)(Qstage + r * LDF + c4) =
            make_float4(tf32r(v.x * qscale), tf32r(v.y * qscale),
                        tf32r(v.z * qscale), tf32r(v.w * qscale));
    }
    __syncthreads();

    uint32_t qf[8][4];
    {
        int r0 = w * 16 + lr;
        #pragma unroll
        for (int j = 0; j < 8; j++) {
            qf[j][0] = fbits(Qstage[r0 * LDF + 8 * j + lc]);
            qf[j][1] = fbits(Qstage[(r0 + 8) * LDF + 8 * j + lc]);
            qf[j][2] = fbits(Qstage[r0 * LDF + 8 * j + 4 + lc]);
            qf[j][3] = fbits(Qstage[(r0 + 8) * LDF + 8 * j + 4 + lc]);
        }
    }
    __syncthreads();   // all qf extracted before buffer 0 is overwritten

    const int nIter = 2 * qt + 2;
    const float* kvb = qkv + (size_t)(b * Tt) * C3 + Cc + h * HSs;

    // copy helper: K/V tile jb -> buffer s
    const int cr = tid >> 2;              // 0..63 via idx math below
    #define ISSUE(jb_, s_) do { \
        const float* kb_ = kvb + (size_t)(jb_) * 64 * C3; \
        uint32_t kd_ = (uint32_t)__cvta_generic_to_shared(sm + (s_) * 2 * BUFF); \
        uint32_t vd_ = kd_ + BUFF * 4; \
        _Pragma("unroll") \
        for (int it = 0; it < 4; it++) { \
            int idx = tid + it * 256; \
            int r = idx >> 4, c4 = (idx & 15) << 2; \
            size_t go = (size_t)r * C3 + c4; \
            uint32_t so = (uint32_t)(r * LDF + c4) * 4u; \
            cp16(kd_ + so, kb_ + go); \
            cp16(vd_ + so, kb_ + Cc + go); \
        } \
        cp_commit(); \
    } while (0)

    ISSUE(0, 0);

    float accO[8][4];
    #pragma unroll
    for (int j = 0; j < 8; j++)
        #pragma unroll
        for (int q = 0; q < 4; q++) accO[j][q] = 0.f;
    float m0 = NEG, m1 = NEG, l0 = 0.f, l1 = 0.f;

    const int rowA = q0 + w * 16 + lr;
    const int rowB = rowA + 8;

    for (int jb = 0; jb < nIter; jb++) {
        const int cur = jb & 1;
        float* Ks = sm + cur * 2 * BUFF;
        float* Vs = Ks + BUFF;

        __syncthreads();                      // prev compute done: other buf reusable
        int nxt = jb + 1 < nIter ? jb + 1 : jb;
        ISSUE(nxt, (jb + 1) & 1);
        cp_wait1();                           // this iter's tiles arrived
        __syncthreads();

        // in-place rna conversion of K tile (score path precision)
        #pragma unroll
        for (int it = 0; it < 4; it++) {
            int idx = tid + it * 256;
            int r = idx >> 4, c4 = (idx & 15) << 2;
            float4 v = *(float4*)(Ks + r * LDF + c4);
            *(float4*)(Ks + r * LDF + c4) =
                make_float4(tf32r(v.x), tf32r(v.y), tf32r(v.z), tf32r(v.w));
        }
        __syncthreads();

        // ---- S = Qf x K^T ----
        float sAcc[8][4];
        #pragma unroll
        for (int j = 0; j < 8; j++)
            #pragma unroll
            for (int q = 0; q < 4; q++) sAcc[j][q] = 0.f;

        #pragma unroll
        for (int ks = 0; ks < 8; ks++) {
            #pragma unroll
            for (int nj = 0; nj < 8; nj++) {
                uint32_t bf[2];
                int n0 = nj * 8 + lr;
                bf[0] = fbits(Ks[n0 * LDF + ks * 8 + lc]);
                bf[1] = fbits(Ks[n0 * LDF + ks * 8 + 4 + lc]);
                mma_tf32(sAcc[nj], qf[ks], bf);
            }
        }

        // ---- causal mask ----
        if (jb * 64 + 63 > q0 + w * 16) {
            #pragma unroll
            for (int nj = 0; nj < 8; nj++) {
                int col = jb * 64 + nj * 8 + 2 * lc;
                if (col > rowA)     sAcc[nj][0] = NEG;
                if (col + 1 > rowA) sAcc[nj][1] = NEG;
                if (col > rowB)     sAcc[nj][2] = NEG;
                if (col + 1 > rowB) sAcc[nj][3] = NEG;
            }
        }

        // ---- online softmax (base 2), registers only ----
        float mxA = NEG, mxB = NEG;
        #pragma unroll
        for (int nj = 0; nj < 8; nj++) {
            mxA = fmaxf(mxA, fmaxf(sAcc[nj][0], sAcc[nj][1]));
            mxB = fmaxf(mxB, fmaxf(sAcc[nj][2], sAcc[nj][3]));
        }
        mxA = fmaxf(mxA, __shfl_xor_sync(0xffffffffu, mxA, 1));
        mxA = fmaxf(mxA, __shfl_xor_sync(0xffffffffu, mxA, 2));
        mxB = fmaxf(mxB, __shfl_xor_sync(0xffffffffu, mxB, 1));
        mxB = fmaxf(mxB, __shfl_xor_sync(0xffffffffu, mxB, 2));

        float mn0 = fmaxf(m0, mxA), mn1 = fmaxf(m1, mxB);
        float al0 = ex2(m0 - mn0), al1 = ex2(m1 - mn1);
        m0 = mn0; m1 = mn1;

        float sumA = 0.f, sumB = 0.f;
        #pragma unroll
        for (int nj = 0; nj < 8; nj++) {
            float e0 = ex2(sAcc[nj][0] - mn0);
            float e1 = ex2(sAcc[nj][1] - mn0);
            float e2 = ex2(sAcc[nj][2] - mn1);
            float e3 = ex2(sAcc[nj][3] - mn1);
            sumA += e0 + e1; sumB += e2 + e3;
            sAcc[nj][0] = tf32r(e0); sAcc[nj][1] = tf32r(e1);
            sAcc[nj][2] = tf32r(e2); sAcc[nj][3] = tf32r(e3);
        }
        sumA += __shfl_xor_sync(0xffffffffu, sumA, 1);
        sumA += __shfl_xor_sync(0xffffffffu, sumA, 2);
        sumB += __shfl_xor_sync(0xffffffffu, sumB, 1);
        sumB += __shfl_xor_sync(0xffffffffu, sumB, 2);
        l0 = l0 * al0 + sumA;
        l1 = l1 * al1 + sumB;

        #pragma unroll
        for (int nj = 0; nj < 8; nj++) {
            accO[nj][0] *= al0; accO[nj][1] *= al0;
            accO[nj][2] *= al1; accO[nj][3] *= al1;
        }

        // ---- P (C-layout) -> A-frags via shfl; O += P * V ----
        const int s1 = (lane & 28) | (lc >> 1);
        const int s2 = s1 + 2;
        const bool odd = lc & 1;
        #pragma unroll
        for (int ks = 0; ks < 8; ks++) {
            float c0 = sAcc[ks][0], c1 = sAcc[ks][1];
            float c2 = sAcc[ks][2], c3 = sAcc[ks][3];
            float t0 = __shfl_sync(0xffffffffu, c0, s1);
            float t1 = __shfl_sync(0xffffffffu, c1, s1);
            float u0 = __shfl_sync(0xffffffffu, c2, s1);
            float u1 = __shfl_sync(0xffffffffu, c3, s1);
            float v0 = __shfl_sync(0xffffffffu, c0, s2);
            float v1 = __shfl_sync(0xffffffffu, c1, s2);
            float w0 = __shfl_sync(0xffffffffu, c2, s2);
            float w1 = __shfl_sync(0xffffffffu, c3, s2);
            uint32_t af[4];
            af[0] = fbits(odd ? t1 : t0);
            af[1] = fbits(odd ? u1 : u0);
            af[2] = fbits(odd ? v1 : v0);
            af[3] = fbits(odd ? w1 : w0);
            #pragma unroll
            for (int nj = 0; nj < 8; nj++) {
                uint32_t bf[2];
                int c0i = nj * 8 + lr;
                bf[0] = fbits(Vs[(ks * 8 + lc) * LDF + c0i]);
                bf[1] = fbits(Vs[(ks * 8 + 4 + lc) * LDF + c0i]);
                mma_tf32(accO[nj], af, bf);
            }
        }
    }

    // drain remaining async group before exit-path stores reuse nothing; harmless
    asm volatile("cp.async.wait_group 0;");

    float rl0 = 1.f / l0, rl1 = 1.f / l1;
    float* obase = out + qrow0 * Cc + h * HSs;
    int r0 = w * 16 + lr;
    #pragma unroll
    for (int nj = 0; nj < 8; nj++) {
        int col = nj * 8 + 2 * lc;
        *(float2*)(obase + (size_t)r0 * Cc + col) =
            make_float2(accO[nj][0] * rl0, accO[nj][1] * rl0);
        *(float2*)(obase + (size_t)(r0 + 8) * Cc + col) =
            make_float2(accO[nj][2] * rl1, accO[nj][3] * rl1);
    }
    #undef ISSUE
}

// ---------------------------------------------------------------------------
extern "C" void kernel_launch(void* const* d_in, const int* in_sizes, int n_in,
                              void* d_out, int out_size)
{
    const float* x      = (const float*)d_in[0];
    const float* w_attn = (const float*)d_in[1];
    const float* w_proj = (const float*)d_in[2];
    float* out = (float*)d_out;

    float *qkv, *att;
    cudaGetSymbolAddress((void**)&qkv, g_qkv);
    cudaGetSymbolAddress((void**)&att, g_att);

    const size_t FLASH_SMEM = (size_t)(4 * BUFF) * sizeof(float);  // 73728 B
    cudaFuncSetAttribute(flash_tf32, cudaFuncAttributeMaxDynamicSharedMemorySize,
                         (int)FLASH_SMEM);

    gemm_tf32<<<dim3(C3 / 128, BT / 128), 256>>>(x, w_attn, qkv, BT, C3, Cc);
    flash_tf32<<<dim3(Tt / 128, NHh, Bb), 256, FLASH_SMEM>>>(qkv, att);
    gemm_tf32<<<dim3(Cc / 128, BT / 128), 256>>>(att, w_proj, out, BT, Cc, Cc);
}

// round 6
// speedup vs baseline: 3.7096x; 1.1313x over previous
#include <cuda_runtime.h>
#include <math.h>
#include <stdint.h>

#define Bb 2
#define Tt 4096
#define Cc 768
#define NHh 12
#define HSs 64
#define BT (Bb*Tt)
#define C3 (3*Cc)

__device__ float g_qkv[(size_t)BT * C3];   // [B*T, 3C]
__device__ float g_att[(size_t)BT * Cc];   // [B*T, C]

__device__ __forceinline__ float tf32r(float x) {
    uint32_t u;
    asm("cvt.rna.tf32.f32 %0, %1;" : "=r"(u) : "f"(x));
    return __uint_as_float(u);
}
__device__ __forceinline__ uint32_t fbits(float x) { return __float_as_uint(x); }
__device__ __forceinline__ float ex2(float x) {
    float r;
    asm("ex2.approx.ftz.f32 %0, %1;" : "=f"(r) : "f"(x));
    return r;
}
__device__ __forceinline__ void cp16(uint32_t dst, const void* src) {
    asm volatile("cp.async.cg.shared.global [%0], [%1], 16;" :: "r"(dst), "l"(src));
}
__device__ __forceinline__ void cp_commit() { asm volatile("cp.async.commit_group;"); }
__device__ __forceinline__ void cp_wait1()  { asm volatile("cp.async.wait_group 1;"); }

__device__ __forceinline__ void mma_tf32(float c[4], const uint32_t a[4], const uint32_t b[2]) {
    asm volatile(
        "mma.sync.aligned.m16n8k8.row.col.f32.tf32.tf32.f32 "
        "{%0,%1,%2,%3},{%4,%5,%6,%7},{%8,%9},{%0,%1,%2,%3};"
        : "+f"(c[0]), "+f"(c[1]), "+f"(c[2]), "+f"(c[3])
        : "r"(a[0]), "r"(a[1]), "r"(a[2]), "r"(a[3]), "r"(b[0]), "r"(b[1]));
}

// ---------------------------------------------------------------------------
// TF32 GEMM: C[M,N]=A[M,K]*B[K,N] row-major. CTA tile 128x256, 8 warps,
// warp tile 64x64 (8 MACs per smem byte). kc=16, double-buffered, 1 sync/chunk.
// Requires M%128==0, N%256==0, K%16==0.
// ---------------------------------------------------------------------------
#define LDA 20     // 16+4 pad: A frag banks unique
#define LDB2 264   // 256+8 pad: B frag banks unique (264%32==8)
#define GA_OFF(s)  ((s) * 128 * LDA)                 // floats
#define GB_OFF(s)  (2 * 128 * LDA + (s) * 16 * LDB2)
#define GT_SMEM_FL (2 * 128 * LDA + 2 * 16 * LDB2)   // 13568 floats = 54272 B

__global__ __launch_bounds__(256)
void gemm_tf32(const float* __restrict__ A, const float* __restrict__ B,
               float* __restrict__ C, int M, int N, int K)
{
    extern __shared__ float smg[];

    const int tid = threadIdx.x;
    const int lane = tid & 31, wid = tid >> 5;
    const int warpM = wid >> 2, warpN = wid & 3;       // 2 x 4
    const int lr = lane >> 2, lc = lane & 3;
    const int brow = blockIdx.y << 7, bcol = blockIdx.x << 8;

    const int ar = tid >> 2;           // 0..63 (+64)
    const int ac = (tid & 3) << 2;     // 0,4,8,12
    const int br = tid >> 6;           // 0..3 (+4,+8,+12)
    const int bc = (tid & 63) << 2;    // 0..252

    const float* Ab = A + (size_t)brow * K;
    const float* Bbp = B + bcol;

    float acc[4][8][4];
    #pragma unroll
    for (int i = 0; i < 4; i++)
        #pragma unroll
        for (int j = 0; j < 8; j++)
            #pragma unroll
            for (int q = 0; q < 4; q++) acc[i][j][q] = 0.f;

    float4 pa0, pa1, pb[4];
    #define LOADT(kt) do { \
        pa0 = *(const float4*)(Ab + (size_t)ar * K + (kt)*16 + ac); \
        pa1 = *(const float4*)(Ab + (size_t)(ar + 64) * K + (kt)*16 + ac); \
        _Pragma("unroll") \
        for (int i = 0; i < 4; i++) \
            pb[i] = *(const float4*)(Bbp + (size_t)((kt)*16 + br + 4*i) * N + bc); \
    } while (0)
    #define STORET(s) do { \
        float* As_ = smg + GA_OFF(s); \
        float* Bs_ = smg + GB_OFF(s); \
        *(float4*)(As_ + ar * LDA + ac) = make_float4(tf32r(pa0.x), tf32r(pa0.y), tf32r(pa0.z), tf32r(pa0.w)); \
        *(float4*)(As_ + (ar + 64) * LDA + ac) = make_float4(tf32r(pa1.x), tf32r(pa1.y), tf32r(pa1.z), tf32r(pa1.w)); \
        _Pragma("unroll") \
        for (int i = 0; i < 4; i++) \
            *(float4*)(Bs_ + (br + 4*i) * LDB2 + bc) = \
                make_float4(tf32r(pb[i].x), tf32r(pb[i].y), tf32r(pb[i].z), tf32r(pb[i].w)); \
    } while (0)

    const int NT = K >> 4;
    LOADT(0);
    STORET(0);
    __syncthreads();

    for (int kt = 0; kt < NT; kt++) {
        const int cur = kt & 1;
        if (kt + 1 < NT) LOADT(kt + 1);
        const float* Ac = smg + GA_OFF(cur);
        const float* Bc = smg + GB_OFF(cur);
        #pragma unroll
        for (int kk = 0; kk < 16; kk += 8) {
            uint32_t af[4][4];
            #pragma unroll
            for (int mt = 0; mt < 4; mt++) {
                int r0 = warpM * 64 + mt * 16 + lr;
                af[mt][0] = fbits(Ac[r0 * LDA + kk + lc]);
                af[mt][1] = fbits(Ac[(r0 + 8) * LDA + kk + lc]);
                af[mt][2] = fbits(Ac[r0 * LDA + kk + 4 + lc]);
                af[mt][3] = fbits(Ac[(r0 + 8) * LDA + kk + 4 + lc]);
            }
            #pragma unroll
            for (int nt = 0; nt < 8; nt++) {
                uint32_t bf[2];
                int c0 = warpN * 64 + nt * 8 + lr;
                bf[0] = fbits(Bc[(kk + lc) * LDB2 + c0]);
                bf[1] = fbits(Bc[(kk + 4 + lc) * LDB2 + c0]);
                #pragma unroll
                for (int mt = 0; mt < 4; mt++)
                    mma_tf32(acc[mt][nt], af[mt], bf);
            }
        }
        if (kt + 1 < NT) STORET((kt + 1) & 1);
        __syncthreads();
    }

    #pragma unroll
    for (int mt = 0; mt < 4; mt++)
        #pragma unroll
        for (int nt = 0; nt < 8; nt++) {
            int row = brow + warpM * 64 + mt * 16 + lr;
            int col = bcol + warpN * 64 + nt * 8 + 2 * lc;
            *(float2*)&C[(size_t)row * N + col] = make_float2(acc[mt][nt][0], acc[mt][nt][1]);
            *(float2*)&C[(size_t)(row + 8) * N + col] = make_float2(acc[mt][nt][2], acc[mt][nt][3]);
        }
    #undef LOADT
    #undef STORET
}

// ---------------------------------------------------------------------------
// Causal flash attention: 256 q/block, 64 keys/iter, 8 warps; warp owns
// 32 q-rows x 64 keys (K/V fragments feed 2 mmas each: 8 MACs/byte).
// Register softmax (base-2), cp.async double-buffered K/V.
// ---------------------------------------------------------------------------
#define LDF 72
#define BUFF (64 * LDF)

__global__ __launch_bounds__(256)
void flash_tf32(const float* __restrict__ qkv, float* __restrict__ out)
{
    extern __shared__ float sm[];
    float* Qstage = sm;   // 256*LDF floats == 4*BUFF (overlaps all K/V buffers)

    const int qt = (int)gridDim.x - 1 - (int)blockIdx.x;  // heavy first
    const int h = blockIdx.y, b = blockIdx.z;
    const int tid = threadIdx.x;
    const int lane = tid & 31, w = tid >> 5;
    const int lr = lane >> 2, lc = lane & 3;
    const float NEG = -1e30f;
    const float qscale = 0.125f * 1.44269504089f;   // 1/sqrt(64) * log2(e)

    const int q0 = qt * 256;
    const size_t qrow0 = (size_t)(b * Tt + q0);
    const float* qbase = qkv + qrow0 * C3 + h * HSs;

    // ---- stage Q (scaled + rna), pull A-frags to registers ----
    #pragma unroll
    for (int it = 0; it < 16; it++) {
        int idx = tid + it * 256;               // 0..4095
        int r = idx >> 4, c4 = (idx & 15) << 2;
        float4 v = *(const float4*)(qbase + (size_t)r * C3 + c4);
        *(float4*)(Qstage + r * LDF + c4) =
            make_float4(tf32r(v.x * qscale), tf32r(v.y * qscale),
                        tf32r(v.z * qscale), tf32r(v.w * qscale));
    }
    __syncthreads();

    uint32_t qf[8][2][4];
    #pragma unroll
    for (int mt = 0; mt < 2; mt++) {
        int r0 = w * 32 + mt * 16 + lr;
        #pragma unroll
        for (int j = 0; j < 8; j++) {
            qf[j][mt][0] = fbits(Qstage[r0 * LDF + 8 * j + lc]);
            qf[j][mt][1] = fbits(Qstage[(r0 + 8) * LDF + 8 * j + lc]);
            qf[j][mt][2] = fbits(Qstage[r0 * LDF + 8 * j + 4 + lc]);
            qf[j][mt][3] = fbits(Qstage[(r0 + 8) * LDF + 8 * j + 4 + lc]);
        }
    }
    __syncthreads();   // qf extracted before buffers overwritten

    const int nIter = 4 * qt + 4;
    const float* kvb = qkv + (size_t)(b * Tt) * C3 + Cc + h * HSs;

    #define ISSUE(jb_, s_) do { \
        const float* kb_ = kvb + (size_t)(jb_) * 64 * C3; \
        uint32_t kd_ = (uint32_t)__cvta_generic_to_shared(sm + (s_) * 2 * BUFF); \
        uint32_t vd_ = kd_ + BUFF * 4; \
        _Pragma("unroll") \
        for (int it = 0; it < 4; it++) { \
            int idx = tid + it * 256; \
            int r = idx >> 4, c4 = (idx & 15) << 2; \
            size_t go = (size_t)r * C3 + c4; \
            uint32_t so = (uint32_t)(r * LDF + c4) * 4u; \
            cp16(kd_ + so, kb_ + go); \
            cp16(vd_ + so, kb_ + Cc + go); \
        } \
        cp_commit(); \
    } while (0)

    ISSUE(0, 0);

    float accO[2][8][4];
    #pragma unroll
    for (int mt = 0; mt < 2; mt++)
        #pragma unroll
        for (int j = 0; j < 8; j++)
            #pragma unroll
            for (int q = 0; q < 4; q++) accO[mt][j][q] = 0.f;
    float mrun[2][2] = {{NEG, NEG}, {NEG, NEG}};
    float lrun[2][2] = {{0.f, 0.f}, {0.f, 0.f}};

    for (int jb = 0; jb < nIter; jb++) {
        const int cur = jb & 1;
        float* Ks = sm + cur * 2 * BUFF;
        float* Vs = Ks + BUFF;

        __syncthreads();
        int nxt = jb + 1 < nIter ? jb + 1 : jb;
        ISSUE(nxt, (jb + 1) & 1);
        cp_wait1();
        __syncthreads();

        // in-place rna conversion of K tile
        #pragma unroll
        for (int it = 0; it < 4; it++) {
            int idx = tid + it * 256;
            int r = idx >> 4, c4 = (idx & 15) << 2;
            float4 v = *(float4*)(Ks + r * LDF + c4);
            *(float4*)(Ks + r * LDF + c4) =
                make_float4(tf32r(v.x), tf32r(v.y), tf32r(v.z), tf32r(v.w));
        }
        __syncthreads();

        // ---- S = Qf x K^T (each bf used by both mt tiles) ----
        float sAcc[2][8][4];
        #pragma unroll
        for (int mt = 0; mt < 2; mt++)
            #pragma unroll
            for (int j = 0; j < 8; j++)
                #pragma unroll
                for (int q = 0; q < 4; q++) sAcc[mt][j][q] = 0.f;

        #pragma unroll
        for (int ks = 0; ks < 8; ks++) {
            #pragma unroll
            for (int nj = 0; nj < 8; nj++) {
                uint32_t bf[2];
                int n0 = nj * 8 + lr;
                bf[0] = fbits(Ks[n0 * LDF + ks * 8 + lc]);
                bf[1] = fbits(Ks[n0 * LDF + ks * 8 + 4 + lc]);
                mma_tf32(sAcc[0][nj], qf[ks][0], bf);
                mma_tf32(sAcc[1][nj], qf[ks][1], bf);
            }
        }

        // ---- causal mask + online softmax per mt ----
        #pragma unroll
        for (int mt = 0; mt < 2; mt++) {
            const int rowA = q0 + w * 32 + mt * 16 + lr;
            const int rowB = rowA + 8;
            if (jb * 64 + 63 > q0 + w * 32 + mt * 16) {
                #pragma unroll
                for (int nj = 0; nj < 8; nj++) {
                    int col = jb * 64 + nj * 8 + 2 * lc;
                    if (col > rowA)     sAcc[mt][nj][0] = NEG;
                    if (col + 1 > rowA) sAcc[mt][nj][1] = NEG;
                    if (col > rowB)     sAcc[mt][nj][2] = NEG;
                    if (col + 1 > rowB) sAcc[mt][nj][3] = NEG;
                }
            }

            float mxA = NEG, mxB = NEG;
            #pragma unroll
            for (int nj = 0; nj < 8; nj++) {
                mxA = fmaxf(mxA, fmaxf(sAcc[mt][nj][0], sAcc[mt][nj][1]));
                mxB = fmaxf(mxB, fmaxf(sAcc[mt][nj][2], sAcc[mt][nj][3]));
            }
            mxA = fmaxf(mxA, __shfl_xor_sync(0xffffffffu, mxA, 1));
            mxA = fmaxf(mxA, __shfl_xor_sync(0xffffffffu, mxA, 2));
            mxB = fmaxf(mxB, __shfl_xor_sync(0xffffffffu, mxB, 1));
            mxB = fmaxf(mxB, __shfl_xor_sync(0xffffffffu, mxB, 2));

            float mn0 = fmaxf(mrun[mt][0], mxA), mn1 = fmaxf(mrun[mt][1], mxB);
            float al0 = ex2(mrun[mt][0] - mn0), al1 = ex2(mrun[mt][1] - mn1);
            mrun[mt][0] = mn0; mrun[mt][1] = mn1;

            float sumA = 0.f, sumB = 0.f;
            #pragma unroll
            for (int nj = 0; nj < 8; nj++) {
                float e0 = ex2(sAcc[mt][nj][0] - mn0);
                float e1 = ex2(sAcc[mt][nj][1] - mn0);
                float e2 = ex2(sAcc[mt][nj][2] - mn1);
                float e3 = ex2(sAcc[mt][nj][3] - mn1);
                sumA += e0 + e1; sumB += e2 + e3;
                sAcc[mt][nj][0] = tf32r(e0); sAcc[mt][nj][1] = tf32r(e1);
                sAcc[mt][nj][2] = tf32r(e2); sAcc[mt][nj][3] = tf32r(e3);
            }
            sumA += __shfl_xor_sync(0xffffffffu, sumA, 1);
            sumA += __shfl_xor_sync(0xffffffffu, sumA, 2);
            sumB += __shfl_xor_sync(0xffffffffu, sumB, 1);
            sumB += __shfl_xor_sync(0xffffffffu, sumB, 2);
            lrun[mt][0] = lrun[mt][0] * al0 + sumA;
            lrun[mt][1] = lrun[mt][1] * al1 + sumB;

            #pragma unroll
            for (int nj = 0; nj < 8; nj++) {
                accO[mt][nj][0] *= al0; accO[mt][nj][1] *= al0;
                accO[mt][nj][2] *= al1; accO[mt][nj][3] *= al1;
            }
        }

        // ---- P -> A-frags via shfl; O += P * V (bf shared by both mt) ----
        const int s1 = (lane & 28) | (lc >> 1);
        const int s2 = s1 + 2;
        const bool odd = lc & 1;
        #pragma unroll
        for (int ks = 0; ks < 8; ks++) {
            uint32_t af[2][4];
            #pragma unroll
            for (int mt = 0; mt < 2; mt++) {
                float c0 = sAcc[mt][ks][0], c1 = sAcc[mt][ks][1];
                float c2 = sAcc[mt][ks][2], c3 = sAcc[mt][ks][3];
                float t0 = __shfl_sync(0xffffffffu, c0, s1);
                float t1 = __shfl_sync(0xffffffffu, c1, s1);
                float u0 = __shfl_sync(0xffffffffu, c2, s1);
                float u1 = __shfl_sync(0xffffffffu, c3, s1);
                float v0 = __shfl_sync(0xffffffffu, c0, s2);
                float v1 = __shfl_sync(0xffffffffu, c1, s2);
                float w0 = __shfl_sync(0xffffffffu, c2, s2);
                float w1 = __shfl_sync(0xffffffffu, c3, s2);
                af[mt][0] = fbits(odd ? t1 : t0);
                af[mt][1] = fbits(odd ? u1 : u0);
                af[mt][2] = fbits(odd ? v1 : v0);
                af[mt][3] = fbits(odd ? w1 : w0);
            }
            #pragma unroll
            for (int nj = 0; nj < 8; nj++) {
                uint32_t bf[2];
                int c0i = nj * 8 + lr;
                bf[0] = fbits(Vs[(ks * 8 + lc) * LDF + c0i]);
                bf[1] = fbits(Vs[(ks * 8 + 4 + lc) * LDF + c0i]);
                mma_tf32(accO[0][nj], af[0], bf);
                mma_tf32(accO[1][nj], af[1], bf);
            }
        }
    }

    asm volatile("cp.async.wait_group 0;");

    // ---- normalize + write O ----
    float* obase = out + qrow0 * Cc + h * HSs;
    #pragma unroll
    for (int mt = 0; mt < 2; mt++) {
        int r0 = w * 32 + mt * 16 + lr;
        float rl0 = 1.f / lrun[mt][0], rl1 = 1.f / lrun[mt][1];
        #pragma unroll
        for (int nj = 0; nj < 8; nj++) {
            int col = nj * 8 + 2 * lc;
            *(float2*)(obase + (size_t)r0 * Cc + col) =
                make_float2(accO[mt][nj][0] * rl0, accO[mt][nj][1] * rl0);
            *(float2*)(obase + (size_t)(r0 + 8) * Cc + col) =
                make_float2(accO[mt][nj][2] * rl1, accO[mt][nj][3] * rl1);
        }
    }
    #undef ISSUE
}

// ---------------------------------------------------------------------------
extern "C" void kernel_launch(void* const* d_in, const int* in_sizes, int n_in,
                              void* d_out, int out_size)
{
    const float* x      = (const float*)d_in[0];
    const float* w_attn = (const float*)d_in[1];
    const float* w_proj = (const float*)d_in[2];
    float* out = (float*)d_out;

    float *qkv, *att;
    cudaGetSymbolAddress((void**)&qkv, g_qkv);
    cudaGetSymbolAddress((void**)&att, g_att);

    const int GEMM_SMEM = GT_SMEM_FL * sizeof(float);          // 54272 B
    const int FLASH_SMEM = 4 * BUFF * sizeof(float);           // 73728 B
    cudaFuncSetAttribute(gemm_tf32, cudaFuncAttributeMaxDynamicSharedMemorySize,
                         GEMM_SMEM);
    cudaFuncSetAttribute(flash_tf32, cudaFuncAttributeMaxDynamicSharedMemorySize,
                         FLASH_SMEM);

    // 1) QKV projection: [8192,768] @ [768,2304]
    gemm_tf32<<<dim3(C3 / 256, BT / 128), 256, GEMM_SMEM>>>(x, w_attn, qkv, BT, C3, Cc);
    // 2) Causal flash attention
    flash_tf32<<<dim3(Tt / 256, NHh, Bb), 256, FLASH_SMEM>>>(qkv, att);
    // 3) Output projection: [8192,768] @ [768,768]
    gemm_tf32<<<dim3(Cc / 256, BT / 128), 256, GEMM_SMEM>>>(att, w_proj, out, BT, Cc, Cc);
}

// round 7
// speedup vs baseline: 6.0677x; 1.6357x over previous
#include <cuda_runtime.h>
#include <cuda_fp16.h>
#include <math.h>
#include <stdint.h>

#define Bb 2
#define Tt 4096
#define Cc 768
#define NHh 12
#define HSs 64
#define BT (Bb*Tt)
#define C3 (3*Cc)

__device__ __half g_qkv[(size_t)BT * C3];   // [B*T, 3C] fp16
__device__ __half g_att[(size_t)BT * Cc];   // [B*T, C]  fp16

__device__ __forceinline__ uint32_t h2u(__half2 h) {
    return *reinterpret_cast<uint32_t*>(&h);
}
__device__ __forceinline__ uint32_t pk(float a, float b) {
    __half2 h = __floats2half2_rn(a, b);
    return h2u(h);
}
__device__ __forceinline__ float ex2(float x) {
    float r;
    asm("ex2.approx.ftz.f32 %0, %1;" : "=f"(r) : "f"(x));
    return r;
}
__device__ __forceinline__ void cp16(uint32_t dst, const void* src) {
    asm volatile("cp.async.cg.shared.global [%0], [%1], 16;" :: "r"(dst), "l"(src));
}
__device__ __forceinline__ void cp_commit() { asm volatile("cp.async.commit_group;"); }
__device__ __forceinline__ void cp_wait1()  { asm volatile("cp.async.wait_group 1;"); }

__device__ __forceinline__ void mma_f16(float c[4], const uint32_t a[4], const uint32_t b[2]) {
    asm volatile(
        "mma.sync.aligned.m16n8k16.row.col.f32.f16.f16.f32 "
        "{%0,%1,%2,%3},{%4,%5,%6,%7},{%8,%9},{%0,%1,%2,%3};"
        : "+f"(c[0]), "+f"(c[1]), "+f"(c[2]), "+f"(c[3])
        : "r"(a[0]), "r"(a[1]), "r"(a[2]), "r"(a[3]), "r"(b[0]), "r"(b[1]));
}
__device__ __forceinline__ void ldsm4(uint32_t r[4], uint32_t saddr) {
    asm volatile("ldmatrix.sync.aligned.m8n8.x4.shared.b16 {%0,%1,%2,%3}, [%4];"
                 : "=r"(r[0]), "=r"(r[1]), "=r"(r[2]), "=r"(r[3]) : "r"(saddr));
}
__device__ __forceinline__ void ldsm4t(uint32_t r[4], uint32_t saddr) {
    asm volatile("ldmatrix.sync.aligned.m8n8.x4.trans.shared.b16 {%0,%1,%2,%3}, [%4];"
                 : "=r"(r[0]), "=r"(r[1]), "=r"(r[2]), "=r"(r[3]) : "r"(saddr));
}
__device__ __forceinline__ uint32_t cvs(const void* p) {
    return (uint32_t)__cvta_generic_to_shared(p);
}

// ---------------------------------------------------------------------------
// fp16 GEMM: C[M,N] = A[M,K]*B[K,N]. CTA 128x128, 8 warps (2x4), warp 64x32.
// kc=32 (2 k-steps of 16), double-buffered smem, 1 sync per chunk.
// A: float or half input; B: float (weights); C: half or float output.
// ---------------------------------------------------------------------------
#define LDAH 40    // A row stride in halfs (32+8)
#define LDBH 136   // B row stride in halfs (128+8)
#define GA_H(s) ((s) * 128 * LDAH)
#define GB_H(s) (2 * 128 * LDAH + (s) * 32 * LDBH)
#define GEMM_SMEM_H (2 * 128 * LDAH + 2 * 32 * LDBH)   // halfs

template <typename TA, typename TC>
__global__ __launch_bounds__(256)
void gemm_f16k(const TA* __restrict__ A, const float* __restrict__ B,
               TC* __restrict__ C, int M, int N, int K)
{
    extern __shared__ __half smh[];

    const int tid = threadIdx.x;
    const int lane = tid & 31, wid = tid >> 5;
    const int warpM = wid >> 2, warpN = wid & 3;
    const int lr = lane >> 2, lc = lane & 3;
    const int brow = blockIdx.y << 7, bcol = blockIdx.x << 7;

    // copy-in indices: A row ar, 16 k's starting k0a; B row kb, 16 n's at n0b
    const int ar = tid >> 1, k0a = (tid & 1) << 4;
    const int kb = tid >> 3, n0b = (tid & 7) << 4;

    const TA* Ab = A + (size_t)(brow + ar) * K + k0a;
    const float* Bbp = B + (size_t)kb * N + bcol + n0b;

    float acc[4][4][4];
    #pragma unroll
    for (int i = 0; i < 4; i++)
        #pragma unroll
        for (int j = 0; j < 4; j++)
            #pragma unroll
            for (int q = 0; q < 4; q++) acc[i][j][q] = 0.f;

    // prefetch regs
    float4 pa[4]; uint4 pah[2]; float4 pb[4];

    #define LOADT(kt) do { \
        if constexpr (sizeof(TA) == 4) { \
            _Pragma("unroll") \
            for (int i = 0; i < 4; i++) \
                pa[i] = *(const float4*)((const float*)Ab + (kt)*32 + i*4); \
        } else { \
            _Pragma("unroll") \
            for (int i = 0; i < 2; i++) \
                pah[i] = *(const uint4*)((const __half*)Ab + (kt)*32 + i*8); \
        } \
        _Pragma("unroll") \
        for (int i = 0; i < 4; i++) \
            pb[i] = *(const float4*)(Bbp + (size_t)((kt)*32) * N + i*4); \
    } while (0)

    #define STORET(s) do { \
        __half* As_ = smh + GA_H(s) + ar * LDAH + k0a; \
        if constexpr (sizeof(TA) == 4) { \
            uint4 u0, u1; \
            u0.x = pk(pa[0].x, pa[0].y); u0.y = pk(pa[0].z, pa[0].w); \
            u0.z = pk(pa[1].x, pa[1].y); u0.w = pk(pa[1].z, pa[1].w); \
            u1.x = pk(pa[2].x, pa[2].y); u1.y = pk(pa[2].z, pa[2].w); \
            u1.z = pk(pa[3].x, pa[3].y); u1.w = pk(pa[3].z, pa[3].w); \
            *(uint4*)(As_) = u0; *(uint4*)(As_ + 8) = u1; \
        } else { \
            *(uint4*)(As_) = pah[0]; *(uint4*)(As_ + 8) = pah[1]; \
        } \
        __half* Bs_ = smh + GB_H(s) + kb * LDBH + n0b; \
        uint4 v0, v1; \
        v0.x = pk(pb[0].x, pb[0].y); v0.y = pk(pb[0].z, pb[0].w); \
        v0.z = pk(pb[1].x, pb[1].y); v0.w = pk(pb[1].z, pb[1].w); \
        v1.x = pk(pb[2].x, pb[2].y); v1.y = pk(pb[2].z, pb[2].w); \
        v1.z = pk(pb[3].x, pb[3].y); v1.w = pk(pb[3].z, pb[3].w); \
        *(uint4*)(Bs_) = v0; *(uint4*)(Bs_ + 8) = v1; \
    } while (0)

    const int NT = K >> 5;
    LOADT(0);
    STORET(0);
    __syncthreads();

    // ldmatrix lane addressing (element offsets, halfs)
    const int aRow = lane & 15, aKoff = (lane & 16) ? 8 : 0;
    const int bRow = (lane & 7) + ((lane & 8) ? 8 : 0);
    const int bNoff = (lane & 16) ? 8 : 0;

    for (int kt = 0; kt < NT; kt++) {
        const int cur = kt & 1;
        if (kt + 1 < NT) LOADT(kt + 1);
        const __half* Ac = smh + GA_H(cur);
        const __half* Bc = smh + GB_H(cur);
        #pragma unroll
        for (int ks = 0; ks < 2; ks++) {
            uint32_t af[4][4];
            #pragma unroll
            for (int mt = 0; mt < 4; mt++)
                ldsm4(af[mt], cvs(Ac + (warpM * 64 + mt * 16 + aRow) * LDAH
                                     + ks * 16 + aKoff));
            uint32_t bf[4][2];
            #pragma unroll
            for (int j2 = 0; j2 < 2; j2++) {
                uint32_t t[4];
                ldsm4t(t, cvs(Bc + (ks * 16 + bRow) * LDBH
                                 + warpN * 32 + j2 * 16 + bNoff));
                bf[2 * j2][0] = t[0]; bf[2 * j2][1] = t[1];
                bf[2 * j2 + 1][0] = t[2]; bf[2 * j2 + 1][1] = t[3];
            }
            #pragma unroll
            for (int mt = 0; mt < 4; mt++)
                #pragma unroll
                for (int nt = 0; nt < 4; nt++)
                    mma_f16(acc[mt][nt], af[mt], bf[nt]);
        }
        if (kt + 1 < NT) STORET((kt + 1) & 1);
        __syncthreads();
    }

    #pragma unroll
    for (int mt = 0; mt < 4; mt++)
        #pragma unroll
        for (int nt = 0; nt < 4; nt++) {
            int row = brow + warpM * 64 + mt * 16 + lr;
            int col = bcol + warpN * 32 + nt * 8 + 2 * lc;
            if constexpr (sizeof(TC) == 2) {
                *(__half2*)&C[(size_t)row * N + col] =
                    __floats2half2_rn(acc[mt][nt][0], acc[mt][nt][1]);
                *(__half2*)&C[(size_t)(row + 8) * N + col] =
                    __floats2half2_rn(acc[mt][nt][2], acc[mt][nt][3]);
            } else {
                *(float2*)&C[(size_t)row * N + col] =
                    make_float2(acc[mt][nt][0], acc[mt][nt][1]);
                *(float2*)&C[(size_t)(row + 8) * N + col] =
                    make_float2(acc[mt][nt][2], acc[mt][nt][3]);
            }
        }
    #undef LOADT
    #undef STORET
}

// ---------------------------------------------------------------------------
// Causal flash attention, fp16 mma (m16n8k16), register softmax (base-2),
// cp.async double-buffered K/V, ldmatrix operand fetch.
// 256 q/block, 8 warps; warp owns 32 q-rows x 64 keys.
// ---------------------------------------------------------------------------
#define LDFH 72                 // smem row stride (halfs)
#define BUFFH (64 * LDFH)       // one 64x64 tile (halfs)

__global__ __launch_bounds__(256)
void flash_f16(const __half* __restrict__ qkv, __half* __restrict__ out)
{
    extern __shared__ __half smf[];
    __half* Qstage = smf;   // 256*LDFH halfs == 4*BUFFH (overlaps K/V bufs)

    const int qt = (int)gridDim.x - 1 - (int)blockIdx.x;  // heavy first
    const int h = blockIdx.y, b = blockIdx.z;
    const int tid = threadIdx.x;
    const int lane = tid & 31, w = tid >> 5;
    const int lr = lane >> 2, lc = lane & 3;
    const float NEG = -1e30f;
    const float qscale = 0.125f * 1.44269504089f;   // 1/sqrt(64) * log2(e)

    const int q0 = qt * 256;
    const size_t qrow0 = (size_t)(b * Tt + q0);
    const __half* qbase = qkv + qrow0 * C3 + h * HSs;

    // ---- stage Q (scaled) into smem ----
    {
        const __half* qr = qbase + (size_t)tid * C3;
        __half* qd = Qstage + tid * LDFH;
        #pragma unroll
        for (int c8 = 0; c8 < 64; c8 += 8) {
            uint4 u = *(const uint4*)(qr + c8);
            __half2* hp = (__half2*)&u;
            #pragma unroll
            for (int q = 0; q < 4; q++) {
                float2 f = __half22float2(hp[q]);
                hp[q] = __floats2half2_rn(f.x * qscale, f.y * qscale);
            }
            *(uint4*)(qd + c8) = u;
        }
    }
    __syncthreads();

    // ---- extract Q A-frags: qf[mt][ks][4] ----
    const int aRow = lane & 15, aKoff = (lane & 16) ? 8 : 0;
    uint32_t qf[2][4][4];
    #pragma unroll
    for (int mt = 0; mt < 2; mt++)
        #pragma unroll
        for (int ks = 0; ks < 4; ks++)
            ldsm4(qf[mt][ks], cvs(Qstage + (w * 32 + mt * 16 + aRow) * LDFH
                                     + ks * 16 + aKoff));
    __syncthreads();   // before buffers are overwritten

    const int nIter = 4 * qt + 4;
    const __half* kvb = qkv + (size_t)(b * Tt) * C3 + Cc + h * HSs;

    #define ISSUE(jb_, s_) do { \
        const __half* kb_ = kvb + (size_t)(jb_) * 64 * C3; \
        uint32_t kd_ = cvs(smf + (s_) * 2 * BUFFH); \
        uint32_t vd_ = kd_ + BUFFH * 2; \
        _Pragma("unroll") \
        for (int it = 0; it < 2; it++) { \
            int idx = tid + it * 256; \
            int r = idx >> 3, c8 = (idx & 7) << 3; \
            size_t go = (size_t)r * C3 + c8; \
            uint32_t so = (uint32_t)(r * LDFH + c8) * 2u; \
            cp16(kd_ + so, kb_ + go); \
            cp16(vd_ + so, kb_ + Cc + go); \
        } \
        cp_commit(); \
    } while (0)

    ISSUE(0, 0);

    float accO[2][8][4];
    #pragma unroll
    for (int mt = 0; mt < 2; mt++)
        #pragma unroll
        for (int j = 0; j < 8; j++)
            #pragma unroll
            for (int q = 0; q < 4; q++) accO[mt][j][q] = 0.f;
    float mrun[2][2] = {{NEG, NEG}, {NEG, NEG}};
    float lrun[2][2] = {{0.f, 0.f}, {0.f, 0.f}};

    // ldmatrix lane addressing for K (non-trans) and V (trans)
    const int kRow = (lane & 7) + ((lane & 8) ? 8 : 0);
    const int kOff = (lane & 16) ? 8 : 0;

    for (int jb = 0; jb < nIter; jb++) {
        const int cur = jb & 1;
        __half* Ks = smf + cur * 2 * BUFFH;
        __half* Vs = Ks + BUFFH;

        __syncthreads();
        int nxt = jb + 1 < nIter ? jb + 1 : jb;
        ISSUE(nxt, (jb + 1) & 1);
        cp_wait1();
        __syncthreads();

        // ---- S = Q x K^T ----
        float sAcc[2][8][4];
        #pragma unroll
        for (int mt = 0; mt < 2; mt++)
            #pragma unroll
            for (int j = 0; j < 8; j++)
                #pragma unroll
                for (int q = 0; q < 4; q++) sAcc[mt][j][q] = 0.f;

        #pragma unroll
        for (int ks = 0; ks < 4; ks++) {
            uint32_t kf[8][2];
            #pragma unroll
            for (int j2 = 0; j2 < 4; j2++) {
                uint32_t t[4];
                // rows: keys j2*16 + kRow; cols: d = ks*16 + kOff
                ldsm4(t, cvs(Ks + (j2 * 16 + kRow) * LDFH + ks * 16 + kOff));
                kf[2 * j2][0] = t[0]; kf[2 * j2][1] = t[2];
                kf[2 * j2 + 1][0] = t[1]; kf[2 * j2 + 1][1] = t[3];
            }
            #pragma unroll
            for (int nj = 0; nj < 8; nj++) {
                mma_f16(sAcc[0][nj], qf[0][ks], kf[nj]);
                mma_f16(sAcc[1][nj], qf[1][ks], kf[nj]);
            }
        }

        // ---- causal mask + online softmax per mt ----
        #pragma unroll
        for (int mt = 0; mt < 2; mt++) {
            const int rowA = q0 + w * 32 + mt * 16 + lr;
            const int rowB = rowA + 8;
            if (jb * 64 + 63 > q0 + w * 32 + mt * 16) {
                #pragma unroll
                for (int nj = 0; nj < 8; nj++) {
                    int col = jb * 64 + nj * 8 + 2 * lc;
                    if (col > rowA)     sAcc[mt][nj][0] = NEG;
                    if (col + 1 > rowA) sAcc[mt][nj][1] = NEG;
                    if (col > rowB)     sAcc[mt][nj][2] = NEG;
                    if (col + 1 > rowB) sAcc[mt][nj][3] = NEG;
                }
            }

            float mxA = NEG, mxB = NEG;
            #pragma unroll
            for (int nj = 0; nj < 8; nj++) {
                mxA = fmaxf(mxA, fmaxf(sAcc[mt][nj][0], sAcc[mt][nj][1]));
                mxB = fmaxf(mxB, fmaxf(sAcc[mt][nj][2], sAcc[mt][nj][3]));
            }
            mxA = fmaxf(mxA, __shfl_xor_sync(0xffffffffu, mxA, 1));
            mxA = fmaxf(mxA, __shfl_xor_sync(0xffffffffu, mxA, 2));
            mxB = fmaxf(mxB, __shfl_xor_sync(0xffffffffu, mxB, 1));
            mxB = fmaxf(mxB, __shfl_xor_sync(0xffffffffu, mxB, 2));

            float mn0 = fmaxf(mrun[mt][0], mxA), mn1 = fmaxf(mrun[mt][1], mxB);
            float al0 = ex2(mrun[mt][0] - mn0), al1 = ex2(mrun[mt][1] - mn1);
            mrun[mt][0] = mn0; mrun[mt][1] = mn1;

            float sumA = 0.f, sumB = 0.f;
            #pragma unroll
            for (int nj = 0; nj < 8; nj++) {
                float e0 = ex2(sAcc[mt][nj][0] - mn0);
                float e1 = ex2(sAcc[mt][nj][1] - mn0);
                float e2 = ex2(sAcc[mt][nj][2] - mn1);
                float e3 = ex2(sAcc[mt][nj][3] - mn1);
                sumA += e0 + e1; sumB += e2 + e3;
                sAcc[mt][nj][0] = e0; sAcc[mt][nj][1] = e1;
                sAcc[mt][nj][2] = e2; sAcc[mt][nj][3] = e3;
            }
            sumA += __shfl_xor_sync(0xffffffffu, sumA, 1);
            sumA += __shfl_xor_sync(0xffffffffu, sumA, 2);
            sumB += __shfl_xor_sync(0xffffffffu, sumB, 1);
            sumB += __shfl_xor_sync(0xffffffffu, sumB, 2);
            lrun[mt][0] = lrun[mt][0] * al0 + sumA;
            lrun[mt][1] = lrun[mt][1] * al1 + sumB;

            #pragma unroll
            for (int nj = 0; nj < 8; nj++) {
                accO[mt][nj][0] *= al0; accO[mt][nj][1] *= al0;
                accO[mt][nj][2] *= al1; accO[mt][nj][3] *= al1;
            }
        }

        // ---- P (C-frag == A-frag layout for k16): pack to half, O += P*V ----
        uint32_t paf[2][4][4];
        #pragma unroll
        for (int mt = 0; mt < 2; mt++)
            #pragma unroll
            for (int ks = 0; ks < 4; ks++) {
                paf[mt][ks][0] = pk(sAcc[mt][2 * ks][0],     sAcc[mt][2 * ks][1]);
                paf[mt][ks][1] = pk(sAcc[mt][2 * ks][2],     sAcc[mt][2 * ks][3]);
                paf[mt][ks][2] = pk(sAcc[mt][2 * ks + 1][0], sAcc[mt][2 * ks + 1][1]);
                paf[mt][ks][3] = pk(sAcc[mt][2 * ks + 1][2], sAcc[mt][2 * ks + 1][3]);
            }
        #pragma unroll
        for (int ks = 0; ks < 4; ks++) {
            uint32_t vf[8][2];
            #pragma unroll
            for (int j2 = 0; j2 < 4; j2++) {
                uint32_t t[4];
                // rows: keys ks*16 + kRow; cols: d = j2*16 + kOff
                ldsm4t(t, cvs(Vs + (ks * 16 + kRow) * LDFH + j2 * 16 + kOff));
                vf[2 * j2][0] = t[0]; vf[2 * j2][1] = t[1];
                vf[2 * j2 + 1][0] = t[2]; vf[2 * j2 + 1][1] = t[3];
            }
            #pragma unroll
            for (int nj = 0; nj < 8; nj++) {
                mma_f16(accO[0][nj], paf[0][ks], vf[nj]);
                mma_f16(accO[1][nj], paf[1][ks], vf[nj]);
            }
        }
    }

    asm volatile("cp.async.wait_group 0;");

    // ---- normalize + write O (half) ----
    __half* obase = out + qrow0 * Cc + h * HSs;
    #pragma unroll
    for (int mt = 0; mt < 2; mt++) {
        int r0 = w * 32 + mt * 16 + lr;
        float rl0 = 1.f / lrun[mt][0], rl1 = 1.f / lrun[mt][1];
        #pragma unroll
        for (int nj = 0; nj < 8; nj++) {
            int col = nj * 8 + 2 * lc;
            *(__half2*)(obase + (size_t)r0 * Cc + col) =
                __floats2half2_rn(accO[mt][nj][0] * rl0, accO[mt][nj][1] * rl0);
            *(__half2*)(obase + (size_t)(r0 + 8) * Cc + col) =
                __floats2half2_rn(accO[mt][nj][2] * rl1, accO[mt][nj][3] * rl1);
        }
    }
    #undef ISSUE
}

// ---------------------------------------------------------------------------
extern "C" void kernel_launch(void* const* d_in, const int* in_sizes, int n_in,
                              void* d_out, int out_size)
{
    const float* x      = (const float*)d_in[0];
    const float* w_attn = (const float*)d_in[1];
    const float* w_proj = (const float*)d_in[2];
    float* out = (float*)d_out;

    __half *qkv, *att;
    cudaGetSymbolAddress((void**)&qkv, g_qkv);
    cudaGetSymbolAddress((void**)&att, g_att);

    const int GEMM_SMEM = GEMM_SMEM_H * sizeof(__half);     // 37888 B
    const int FLASH_SMEM = 4 * BUFFH * sizeof(__half);      // 36864 B
    cudaFuncSetAttribute((const void*)gemm_f16k<float, __half>,
                         cudaFuncAttributeMaxDynamicSharedMemorySize, GEMM_SMEM);
    cudaFuncSetAttribute((const void*)gemm_f16k<__half, float>,
                         cudaFuncAttributeMaxDynamicSharedMemorySize, GEMM_SMEM);
    cudaFuncSetAttribute((const void*)flash_f16,
                         cudaFuncAttributeMaxDynamicSharedMemorySize, FLASH_SMEM);

    // 1) QKV projection: [8192,768] @ [768,2304] -> half
    gemm_f16k<float, __half><<<dim3(C3 / 128, BT / 128), 256, GEMM_SMEM>>>(
        x, w_attn, qkv, BT, C3, Cc);
    // 2) Causal flash attention (fp16 tensor cores) -> half
    flash_f16<<<dim3(Tt / 256, NHh, Bb), 256, FLASH_SMEM>>>(qkv, att);
    // 3) Output projection: [8192,768] @ [768,768] -> float
    gemm_f16k<__half, float><<<dim3(Cc / 128, BT / 128), 256, GEMM_SMEM>>>(
        att, w_proj, out, BT, Cc, Cc);
}